// round 14
// baseline (speedup 1.0000x reference)
#include <cuda_runtime.h>
#include <cuda_fp16.h>
#include <math.h>

#define NA 128
#define NB 2
#define EE 512
#define HH 1024
#define GG 50
#define MROWS (NA*NA*NB)          // 32768
#define AW ((size_t)MROWS*HH/2)   // u32 words per fp16 activation array
#define WW ((size_t)HH*HH/2)      // u32 words per fp16 weight matrix
#define KT 64                     // 16-wide k tiles per row (HH/16)
// fragment tile index: 16x16 tile = 128 u32, laid out lane*4 + reg
#define FIDX(rt, kt) ((((size_t)(rt)) * KT + (kt)) * 128)

// -------- device scratch (no allocations allowed) --------
__device__ float d_g[(size_t)MROWS*GG];
__device__ float d_PQ[2*NA*NB*HH];
__device__ float d_Wg[GG*HH];
__device__ float d_b0[HH];
__device__ float d_eP[NA*NB];
__device__ float d_part[(size_t)MROWS*16];     // per-(row, n-tile, col-half) partial dots
__device__ unsigned d_fHiA[AW];
__device__ unsigned d_fLoA[AW];
__device__ unsigned d_fHiB[AW];
__device__ unsigned d_fLoB[AW];
__device__ unsigned d_Wt[6*WW];

__device__ __forceinline__ float gelu_exact(float x) { return x * normcdff(x); }

__device__ __forceinline__ unsigned smem_u32(const void* p) {
    unsigned a;
    asm("{ .reg .u64 t; cvta.to.shared.u64 t, %1; cvt.u32.u64 %0, t; }" : "=r"(a) : "l"(p));
    return a;
}
__device__ __forceinline__ void cp16(unsigned saddr, const void* g) {
    asm volatile("cp.async.cg.shared.global [%0], [%1], 16;" :: "r"(saddr), "l"(g));
}
__device__ __forceinline__ void ldsm4(unsigned addr, unsigned* r) {
    asm volatile("ldmatrix.sync.aligned.m8n8.x4.shared.b16 {%0,%1,%2,%3}, [%4];"
                 : "=r"(r[0]), "=r"(r[1]), "=r"(r[2]), "=r"(r[3]) : "r"(addr));
}
__device__ __forceinline__ void mma16816(float* c, const unsigned* a, unsigned b0, unsigned b1) {
    asm volatile("mma.sync.aligned.m16n8k16.row.col.f32.f16.f16.f32 "
                 "{%0,%1,%2,%3}, {%4,%5,%6,%7}, {%8,%9}, {%0,%1,%2,%3};"
                 : "+f"(c[0]), "+f"(c[1]), "+f"(c[2]), "+f"(c[3])
                 : "r"(a[0]), "r"(a[1]), "r"(a[2]), "r"(a[3]), "r"(b0), "r"(b1));
}
__device__ __forceinline__ unsigned pack_hi(float v0, float v1, float& l0, float& l1) {
    __half a = __float2half_rn(v0), b = __float2half_rn(v1);
    l0 = v0 - __half2float(a);
    l1 = v1 - __half2float(b);
    return ((unsigned)__half_as_ushort(b) << 16) | __half_as_ushort(a);
}
__device__ __forceinline__ unsigned pack_lo(float l0, float l1) {
    return ((unsigned)__half_as_ushort(__float2half_rn(l1)) << 16)
         | __half_as_ushort(__float2half_rn(l0));
}
__device__ __forceinline__ unsigned pack_h(float v0, float v1) {
    return ((unsigned)__half_as_ushort(__float2half_rn(v1)) << 16)
         | __half_as_ushort(__float2half_rn(v0));
}
__device__ __forceinline__ float hf_lo(unsigned w) {
    return __half2float(__ushort_as_half((unsigned short)(w & 0xffffu)));
}
__device__ __forceinline__ float hf_hi(unsigned w) {
    return __half2float(__ushort_as_half((unsigned short)(w >> 16)));
}

// ================= prologue kernels =================
__global__ void rbf_kernel(const float* __restrict__ dist) {
    int idx = blockIdx.x * blockDim.x + threadIdx.x;
    if (idx >= MROWS * GG) return;
    int m = idx / GG, k = idx - m * GG;
    const float delta = 12.0f / 49.0f;
    const float coeff = -0.5f / (delta * delta);
    float t = dist[m] - delta * (float)k;
    d_g[idx] = expf(coeff * t * t);
}

__global__ void bias0_kernel(const float* __restrict__ Win3,
                             const float* __restrict__ bin,
                             const float* __restrict__ rbf_b) {
    int h = blockIdx.x * blockDim.x + threadIdx.x;
    if (h >= HH) return;
    float s = bin[h];
    for (int e = 0; e < EE; e++) s += rbf_b[e] * Win3[(size_t)e * HH + h];
    d_b0[h] = s;
}

#define SBM 64
#define SBN 64
#define SBK 16
__global__ __launch_bounds__(256)
void sgemm64(const float* __restrict__ A, const float* __restrict__ W,
             float* __restrict__ out, int M, int N, int K,
             size_t wstride, size_t ostride)
{
    W += blockIdx.z * wstride;
    out += blockIdx.z * ostride;
    __shared__ float As[SBK][SBM];
    __shared__ float Bs[SBK][SBN];
    int tid = threadIdx.x;
    int tx = tid & 15, ty = tid >> 4;
    int bm = blockIdx.x * SBM, bn = blockIdx.y * SBN;
    float acc[4][4] = {};
    int arow = tid >> 2, acol = (tid & 3) * 4;
    int brow = tid >> 4, bcol = (tid & 15) * 4;
    for (int k0 = 0; k0 < K; k0 += SBK) {
        float4 va = make_float4(0.f, 0.f, 0.f, 0.f);
        if (bm + arow < M) va = *(const float4*)(A + (size_t)(bm + arow) * K + k0 + acol);
        As[acol + 0][arow] = va.x; As[acol + 1][arow] = va.y;
        As[acol + 2][arow] = va.z; As[acol + 3][arow] = va.w;
        *(float4*)&Bs[brow][bcol] = *(const float4*)(W + (size_t)(k0 + brow) * N + bn + bcol);
        __syncthreads();
        #pragma unroll
        for (int kk = 0; kk < SBK; kk++) {
            float a[4], b[4];
            #pragma unroll
            for (int i = 0; i < 4; i++) a[i] = As[kk][ty * 4 + i];
            #pragma unroll
            for (int j = 0; j < 4; j++) b[j] = Bs[kk][tx * 4 + j];
            #pragma unroll
            for (int i = 0; i < 4; i++)
                #pragma unroll
                for (int j = 0; j < 4; j++)
                    acc[i][j] = fmaf(a[i], b[j], acc[i][j]);
        }
        __syncthreads();
    }
    #pragma unroll
    for (int i = 0; i < 4; i++) {
        int row = bm + ty * 4 + i;
        if (row < M)
            #pragma unroll
            for (int j = 0; j < 4; j++)
                out[(size_t)row * N + bn + tx * 4 + j] = acc[i][j];
    }
}

// h0: write gelu(g@Wg + P + Q + b0) as fp16 hi/lo split in FRAGMENT layout
__global__ __launch_bounds__(256)
void h0_kernel(unsigned* __restrict__ oHi, unsigned* __restrict__ oLo)
{
    __shared__ float Gs[64][52];
    __shared__ float Ws[52][64];
    int tid = threadIdx.x;
    int bm = blockIdx.x * 64, bn = blockIdx.y * 64;
    for (int idx = tid; idx < 64 * GG; idx += 256) {
        int r = idx / GG, k = idx - r * GG;
        Gs[r][k] = d_g[(size_t)(bm + r) * GG + k];
    }
    for (int idx = tid; idx < GG * 64; idx += 256) {
        int k = idx >> 6, n = idx & 63;
        Ws[k][n] = d_Wg[k * HH + bn + n];
    }
    __syncthreads();
    int tx = tid & 15, ty = tid >> 4;
    float acc[4][4] = {};
    #pragma unroll 10
    for (int k = 0; k < GG; k++) {
        float a[4], b[4];
        #pragma unroll
        for (int i = 0; i < 4; i++) a[i] = Gs[ty * 4 + i][k];
        #pragma unroll
        for (int j = 0; j < 4; j++) b[j] = Ws[k][tx * 4 + j];
        #pragma unroll
        for (int i = 0; i < 4; i++)
            #pragma unroll
            for (int j = 0; j < 4; j++)
                acc[i][j] = fmaf(a[i], b[j], acc[i][j]);
    }
    const float* P = d_PQ;
    const float* Q = d_PQ + NA * NB * HH;
    #pragma unroll
    for (int i = 0; i < 4; i++) {
        int m = bm + ty * 4 + i;
        int bb = m & (NB - 1);
        int jat = (m / NB) & (NA - 1);
        int iat = m / (NB * NA);
        int col0 = bn + tx * 4;
        float v[4];
        #pragma unroll
        for (int j = 0; j < 4; j++) {
            int col = col0 + j;
            float t = acc[i][j] + P[(iat * NB + bb) * HH + col]
                    + Q[(jat * NB + bb) * HH + col] + d_b0[col];
            v[j] = gelu_exact(t);
        }
        int inrow = m & 15;
        #pragma unroll
        for (int jp = 0; jp < 2; jp++) {
            int col = col0 + jp * 2;
            unsigned off = (unsigned)(((inrow & 7) * 4 + ((col >> 1) & 3)) * 4
                         + ((inrow >> 3) & 1) + (((col >> 3) & 1) << 1));
            size_t idx = FIDX(m >> 4, col >> 4) + off;
            float l0, l1;
            unsigned hw = pack_hi(v[jp * 2], v[jp * 2 + 1], l0, l1);
            oHi[idx] = hw;
            oLo[idx] = pack_lo(l0, l1);
        }
    }
}

// weight prep: W[K][N] fp32 -> Wt[N][K] single fp16 (u32 k-pairs)
__global__ __launch_bounds__(256)
void prep_w(const float* __restrict__ We, const float* __restrict__ Wf,
            unsigned* __restrict__ wt)
{
    __shared__ float ts[64][33];
    int z = blockIdx.z;
    const float* W = (z < 3) ? We + (size_t)z * HH * HH : Wf + (size_t)(z - 3) * HH * HH;
    int k0 = blockIdx.x * 64, n0 = blockIdx.y * 32;
    int tid = threadIdx.x;
    #pragma unroll
    for (int i = 0; i < 8; i++) {
        int r = (tid >> 5) + i * 8, c = tid & 31;
        ts[r][c] = W[(size_t)(k0 + r) * HH + n0 + c];
    }
    __syncthreads();
    size_t zo = (size_t)z * WW;
    #pragma unroll
    for (int i = 0; i < 4; i++) {
        int on = (tid >> 5) + i * 8;
        int ok = tid & 31;
        float v0 = ts[ok * 2][on], v1 = ts[ok * 2 + 1][on];
        size_t oidx = zo + (size_t)(n0 + on) * (HH / 2) + (k0 >> 1) + ok;
        wt[oidx] = pack_h(v0, v1);
    }
}

// ========= fp16 2-pass mma GEMM layer: A direct-from-gmem fragments =========
// next = res + gelu((Ah+Al)@W^T + bias); res reconstructed from Ah/Al fragments.
// CTA tile 128x128, 256 threads = 8 warps (4m x 2n), warp tile 32x64.
// A: fragment-major tiles (LDG.128/thread), B: cp.async smem + ldmatrix.
// Last layer: fused partial dot with Wout -> d_part[row*16 + nt_blk*2 + wn].
#define SMSTR 80                   // 64B data + 16B pad (conflict-free ldmatrix)
#define TILEB (128*SMSTR)          // 10240 B
#define NCHUNK 32
#define NSTAGE 4
#define DSMEM_BYTES (NSTAGE*TILEB)  // 40960 (B only)

__global__ __launch_bounds__(256, 2)
void mma_layer(const unsigned* __restrict__ AhF, const unsigned* __restrict__ AlF,
               const uint4* __restrict__ Bw,
               const float* __restrict__ bias,
               unsigned* __restrict__ oHi, unsigned* __restrict__ oLo,
               const float* __restrict__ wout, float* __restrict__ part,
               int lastLayer)
{
    extern __shared__ char dsm[];
    __shared__ float s_bias[128];
    __shared__ float s_wout[128];
    unsigned base = smem_u32(dsm);

    int tid = threadIdx.x;
    int nt_blk = blockIdx.x, mt_blk = blockIdx.y;
    if (tid < 128) {
        s_bias[tid] = bias[nt_blk * 128 + tid];
        if (lastLayer) s_wout[tid] = wout[nt_blk * 128 + tid];
    }

    int wid = tid >> 5, lane = tid & 31;
    int wm = wid & 3, wn = wid >> 2;
    int rowtile0 = mt_blk * 8 + wm * 2;

    float acc[2][8][4];
    #pragma unroll
    for (int i = 0; i < 2; i++)
        #pragma unroll
        for (int j = 0; j < 8; j++)
            #pragma unroll
            for (int k = 0; k < 4; k++) acc[i][j][k] = 0.f;

    const uint4* gB = Bw + (size_t)(nt_blk * 128) * 128;  // 128 uint4 per n-row

    int ldrow = tid >> 1;                // B stage fill: 2 cp16 per thread
    // ldmatrix lane addressing for B
    int g = lane >> 3, lr = lane & 7;
    unsigned boff0 = (unsigned)((wn * 64 + (g >> 1) * 8 + lr) * SMSTR + (g & 1) * 16);

    // issue B chunks 0..2
    #pragma unroll
    for (int pc = 0; pc < 3; pc++) {
        unsigned sb = base + pc * TILEB;
        #pragma unroll
        for (int p = 0; p < 2; p++) {
            int idx = tid + p * 256;
            int row = idx >> 2, seg = idx & 3;
            cp16(sb + (unsigned)(row * SMSTR + seg * 16),
                 gB + (size_t)row * 128 + pc * 4 + seg);
        }
        asm volatile("cp.async.commit_group;");
    }

    int stage = 0;
    for (int kc = 0; kc < NCHUNK; kc++) {
        if (kc + 3 < NCHUNK) {
            unsigned sb = base + ((stage + 3) & 3) * TILEB;
            #pragma unroll
            for (int p = 0; p < 2; p++) {
                int idx = tid + p * 256;
                int row = idx >> 2, seg = idx & 3;
                cp16(sb + (unsigned)(row * SMSTR + seg * 16),
                     gB + (size_t)row * 128 + (kc + 3) * 4 + seg);
            }
            asm volatile("cp.async.commit_group;");
            asm volatile("cp.async.wait_group 3;");
        } else if (kc + 2 < NCHUNK) {
            asm volatile("cp.async.wait_group 2;");
        } else if (kc + 1 < NCHUNK) {
            asm volatile("cp.async.wait_group 1;");
        } else {
            asm volatile("cp.async.wait_group 0;");
        }
        __syncthreads();

        unsigned bb = base + stage * TILEB;
        #pragma unroll
        for (int ks = 0; ks < 2; ks++) {
            int kt = kc * 2 + ks;
            uint4 ah[2], al[2];
            #pragma unroll
            for (int mt = 0; mt < 2; mt++) {
                size_t ai = FIDX(rowtile0 + mt, kt) + lane * 4;
                ah[mt] = *(const uint4*)(AhF + ai);
                al[mt] = *(const uint4*)(AlF + ai);
            }
            unsigned b[4][4];
            unsigned kkb = ks * 32;
            #pragma unroll
            for (int p = 0; p < 4; p++)
                ldsm4(bb + boff0 + kkb + p * (16 * SMSTR), b[p]);
            #pragma unroll
            for (int mt = 0; mt < 2; mt++)
                #pragma unroll
                for (int nt = 0; nt < 8; nt++)
                    mma16816(acc[mt][nt], (const unsigned*)&ah[mt],
                             b[nt >> 1][(nt & 1) * 2], b[nt >> 1][(nt & 1) * 2 + 1]);
            #pragma unroll
            for (int mt = 0; mt < 2; mt++)
                #pragma unroll
                for (int nt = 0; nt < 8; nt++)
                    mma16816(acc[mt][nt], (const unsigned*)&al[mt],
                             b[nt >> 1][(nt & 1) * 2], b[nt >> 1][(nt & 1) * 2 + 1]);
        }
        __syncthreads();
        stage = (stage + 1) & 3;
    }

    // ===== epilogue (fragment-major in AND out) =====
    #pragma unroll
    for (int mt = 0; mt < 2; mt++) {
        float pd0 = 0.f, pd1 = 0.f;   // last-layer dots for half0/half1 rows
        #pragma unroll
        for (int t = 0; t < 4; t++) {
            int kt_out = nt_blk * 8 + wn * 4 + t;
            size_t idx = FIDX(rowtile0 + mt, kt_out) + lane * 4;
            uint4 hw4 = *(const uint4*)(AhF + idx);
            uint4 lw4 = *(const uint4*)(AlF + idx);
            int cl = wn * 64 + t * 16 + (lane & 3) * 2;

            // x: half0, nt=2t | y: half1, nt=2t | z: half0, nt=2t+1 | w: half1, nt=2t+1
            float vx0 = hf_lo(hw4.x) + hf_lo(lw4.x) + gelu_exact(acc[mt][2*t][0] + s_bias[cl]);
            float vx1 = hf_hi(hw4.x) + hf_hi(lw4.x) + gelu_exact(acc[mt][2*t][1] + s_bias[cl + 1]);
            float vy0 = hf_lo(hw4.y) + hf_lo(lw4.y) + gelu_exact(acc[mt][2*t][2] + s_bias[cl]);
            float vy1 = hf_hi(hw4.y) + hf_hi(lw4.y) + gelu_exact(acc[mt][2*t][3] + s_bias[cl + 1]);
            float vz0 = hf_lo(hw4.z) + hf_lo(lw4.z) + gelu_exact(acc[mt][2*t+1][0] + s_bias[cl + 8]);
            float vz1 = hf_hi(hw4.z) + hf_hi(lw4.z) + gelu_exact(acc[mt][2*t+1][1] + s_bias[cl + 9]);
            float vw0 = hf_lo(hw4.w) + hf_lo(lw4.w) + gelu_exact(acc[mt][2*t+1][2] + s_bias[cl + 8]);
            float vw1 = hf_hi(hw4.w) + hf_hi(lw4.w) + gelu_exact(acc[mt][2*t+1][3] + s_bias[cl + 9]);

            if (lastLayer) {
                pd0 += vx0 * s_wout[cl] + vx1 * s_wout[cl + 1]
                     + vz0 * s_wout[cl + 8] + vz1 * s_wout[cl + 9];
                pd1 += vy0 * s_wout[cl] + vy1 * s_wout[cl + 1]
                     + vw0 * s_wout[cl + 8] + vw1 * s_wout[cl + 9];
            } else {
                float l0, l1;
                uint4 oh, ol;
                oh.x = pack_hi(vx0, vx1, l0, l1); ol.x = pack_lo(l0, l1);
                oh.y = pack_hi(vy0, vy1, l0, l1); ol.y = pack_lo(l0, l1);
                oh.z = pack_hi(vz0, vz1, l0, l1); ol.z = pack_lo(l0, l1);
                oh.w = pack_hi(vw0, vw1, l0, l1); ol.w = pack_lo(l0, l1);
                *(uint4*)(oHi + idx) = oh;
                *(uint4*)(oLo + idx) = ol;
            }
        }
        if (lastLayer) {
            pd0 += __shfl_xor_sync(0xffffffffu, pd0, 1);
            pd0 += __shfl_xor_sync(0xffffffffu, pd0, 2);
            pd1 += __shfl_xor_sync(0xffffffffu, pd1, 1);
            pd1 += __shfl_xor_sync(0xffffffffu, pd1, 2);
            if ((lane & 3) == 0) {
                int row0 = mt_blk * 128 + wm * 32 + mt * 16 + (lane >> 2);
                part[(size_t)row0 * 16 + nt_blk * 2 + wn] = pd0;
                part[(size_t)(row0 + 8) * 16 + nt_blk * 2 + wn] = pd1;
            }
        }
    }
}

// ========= final reduction over partial dots (2MB input, deterministic) =========
__global__ __launch_bounds__(128)
void reduce2(const float* __restrict__ part, const float* __restrict__ bout,
             const int* __restrict__ mask, const float* __restrict__ vec_hat,
             float* __restrict__ out, int mode)
{
    __shared__ float sred[4][4];
    int tid = threadIdx.x;
    int jb = blockIdx.x;
    int j = jb / NB, b = jb % NB;
    int warp = tid >> 5, lane = tid & 31;
    float bo = bout[0];
    bool mj = mask[b * NA + j] != 0;

    int i = tid;   // 0..127 = one atom index each
    size_t m = ((size_t)(i * NA + j)) * NB + b;
    float dot = 0.f;
    #pragma unroll
    for (int t = 0; t < 16; t++) dot += part[m * 16 + t];
    float entry = (mj && mask[b * NA + i] != 0) ? 1.0f : 0.0f;
    float val = (dot + bo) * entry;

    float e = val, fx = 0.f, fy = 0.f, fz = 0.f;
    if (mode == 1) {
        const float* v = vec_hat + m * 3;
        fx = val * v[0]; fy = val * v[1]; fz = val * v[2];
    }
    #pragma unroll
    for (int o = 16; o > 0; o >>= 1) {
        e  += __shfl_xor_sync(0xffffffffu, e,  o);
        fx += __shfl_xor_sync(0xffffffffu, fx, o);
        fy += __shfl_xor_sync(0xffffffffu, fy, o);
        fz += __shfl_xor_sync(0xffffffffu, fz, o);
    }
    if (lane == 0) { sred[warp][0] = e; sred[warp][1] = fx; sred[warp][2] = fy; sred[warp][3] = fz; }
    __syncthreads();
    if (tid == 0) {
        float a0 = 0, a1 = 0, a2 = 0, a3 = 0;
        for (int w = 0; w < 4; w++) { a0 += sred[w][0]; a1 += sred[w][1]; a2 += sred[w][2]; a3 += sred[w][3]; }
        if (mode == 0) d_eP[jb] = a0;
        else {
            int o = 2 + (b * NA + j) * 3;
            out[o + 0] = a1 / 60.0f; out[o + 1] = a2 / 60.0f; out[o + 2] = a3 / 60.0f;
        }
    }
}

__global__ void energy_kernel(float* __restrict__ out) {
    int tid = threadIdx.x;
    int b = tid >> 5, lane = tid & 31;
    if (b >= NB) return;
    float s = 0.f;
    for (int j = lane; j < NA; j += 32) s += d_eP[j * NB + b];
    #pragma unroll
    for (int o = 16; o > 0; o >>= 1) s += __shfl_xor_sync(0xffffffffu, s, o);
    if (lane == 0) out[b] = s / 3600.0f;
}

// ========= launch =========
extern "C" void kernel_launch(void* const* d_in, const int* in_sizes, int n_in,
                              void* d_out, int out_size)
{
    const float* x       = (const float*)d_in[0];
    const float* dist    = (const float*)d_in[1];
    const float* vec_hat = (const float*)d_in[2];
    const int*   mask    = (const int*)d_in[3];   // bool promoted to int32
    const float* rbf_W   = (const float*)d_in[4];
    const float* rbf_b   = (const float*)d_in[5];
    const float* Win[2]  = {(const float*)d_in[6],  (const float*)d_in[12]};
    const float* bin[2]  = {(const float*)d_in[7],  (const float*)d_in[13]};
    const float* Wh[2]   = {(const float*)d_in[8],  (const float*)d_in[14]};
    const float* bh[2]   = {(const float*)d_in[9],  (const float*)d_in[15]};
    const float* Wout[2] = {(const float*)d_in[10], (const float*)d_in[16]};
    const float* bout[2] = {(const float*)d_in[11], (const float*)d_in[17]};
    int L = in_sizes[8] / (HH * HH);
    float* out = (float*)d_out;

    static int attr_set = 0;
    if (!attr_set) {
        cudaFuncSetAttribute(mma_layer, cudaFuncAttributeMaxDynamicSharedMemorySize, DSMEM_BYTES);
        attr_set = 1;
    }

    float *PQ, *Wg, *partp;
    unsigned *fHiA, *fLoA, *fHiB, *fLoB, *Wt;
    cudaGetSymbolAddress((void**)&PQ, d_PQ);
    cudaGetSymbolAddress((void**)&Wg, d_Wg);
    cudaGetSymbolAddress((void**)&partp, d_part);
    cudaGetSymbolAddress((void**)&fHiA, d_fHiA);
    cudaGetSymbolAddress((void**)&fLoA, d_fLoA);
    cudaGetSymbolAddress((void**)&fHiB, d_fHiB);
    cudaGetSymbolAddress((void**)&fLoB, d_fLoB);
    cudaGetSymbolAddress((void**)&Wt, d_Wt);

    rbf_kernel<<<(MROWS * GG + 255) / 256, 256>>>(dist);
    prep_w<<<dim3(16, 32, 6), 256>>>(Wh[0], Wh[1], Wt);

    for (int mlp = 0; mlp < 2; mlp++) {
        const float* W1 = Win[mlp];
        const float* W3 = Win[mlp] + (size_t)2 * EE * HH;

        // P and Q in one launch (z selects Win row-slice + output half)
        sgemm64<<<dim3(4, 16, 2), 256>>>(x, W1, PQ, NA * NB, HH, EE,
                                         (size_t)EE * HH, (size_t)NA * NB * HH);
        sgemm64<<<dim3(1, 16, 1), 256>>>(rbf_W, W3, Wg, GG, HH, EE, 0, 0);
        bias0_kernel<<<4, 256>>>(W3, bin[mlp], rbf_b);

        h0_kernel<<<dim3(MROWS / 64, HH / 64), 256>>>(fHiA, fLoA);

        unsigned* curHi = fHiA; unsigned* curLo = fLoA;
        unsigned* nxtHi = fHiB; unsigned* nxtLo = fLoB;
        for (int l = 0; l < L; l++) {
            size_t zo = (size_t)(mlp * 3 + l) * WW;
            int last = (l == L - 1) ? 1 : 0;
            mma_layer<<<dim3(HH / 128, MROWS / 128), 256, DSMEM_BYTES>>>(
                curHi, curLo,
                (const uint4*)(Wt + zo),
                bh[mlp] + (size_t)l * HH, nxtHi, nxtLo,
                Wout[mlp], partp, last);
            unsigned* t1 = curHi; curHi = nxtHi; nxtHi = t1;
            unsigned* t2 = curLo; curLo = nxtLo; nxtLo = t2;
        }

        reduce2<<<NA * NB, 128>>>(partp, bout[mlp], mask, vec_hat, out, mlp);
    }

    energy_kernel<<<1, 64>>>(out);
}

// round 15
// speedup vs baseline: 1.1264x; 1.1264x over previous
#include <cuda_runtime.h>
#include <cuda_fp16.h>
#include <math.h>

#define NA 128
#define NB 2
#define EE 512
#define HH 1024
#define GG 50
#define MROWS (NA*NA*NB)          // 32768
#define AW ((size_t)MROWS*HH/2)   // u32 words per fp16 activation array
#define WW ((size_t)HH*HH/2)      // u32 words per fp16 weight matrix
#define KT 64                     // 16-wide k tiles per row (HH/16)
// fragment tile index: 16x16 tile = 128 u32, laid out lane*4 + reg
#define FIDX(rt, kt) ((((size_t)(rt)) * KT + (kt)) * 128)

// -------- device scratch (no allocations allowed) --------
__device__ float d_g[(size_t)MROWS*GG];
__device__ float d_PQ[2*NA*NB*HH];
__device__ float d_Wg[GG*HH];
__device__ float d_b0[HH];
__device__ float d_eP[NA*NB];
__device__ float d_part[(size_t)MROWS*16];     // per-(row, n-tile, col-half) partial dots
__device__ unsigned d_fHiA[AW];
__device__ unsigned d_fLoA[AW];
__device__ unsigned d_fHiB[AW];
__device__ unsigned d_fLoB[AW];
__device__ unsigned d_Wt[6*WW];

__device__ __forceinline__ float gelu_exact(float x) { return x * normcdff(x); }

__device__ __forceinline__ unsigned smem_u32(const void* p) {
    unsigned a;
    asm("{ .reg .u64 t; cvta.to.shared.u64 t, %1; cvt.u32.u64 %0, t; }" : "=r"(a) : "l"(p));
    return a;
}
__device__ __forceinline__ void cp16(unsigned saddr, const void* g) {
    asm volatile("cp.async.cg.shared.global [%0], [%1], 16;" :: "r"(saddr), "l"(g));
}
__device__ __forceinline__ void ldsm4(unsigned addr, unsigned* r) {
    asm volatile("ldmatrix.sync.aligned.m8n8.x4.shared.b16 {%0,%1,%2,%3}, [%4];"
                 : "=r"(r[0]), "=r"(r[1]), "=r"(r[2]), "=r"(r[3]) : "r"(addr));
}
__device__ __forceinline__ void mma16816(float* c, const unsigned* a, unsigned b0, unsigned b1) {
    asm volatile("mma.sync.aligned.m16n8k16.row.col.f32.f16.f16.f32 "
                 "{%0,%1,%2,%3}, {%4,%5,%6,%7}, {%8,%9}, {%0,%1,%2,%3};"
                 : "+f"(c[0]), "+f"(c[1]), "+f"(c[2]), "+f"(c[3])
                 : "r"(a[0]), "r"(a[1]), "r"(a[2]), "r"(a[3]), "r"(b0), "r"(b1));
}
__device__ __forceinline__ unsigned pack_hi(float v0, float v1, float& l0, float& l1) {
    __half a = __float2half_rn(v0), b = __float2half_rn(v1);
    l0 = v0 - __half2float(a);
    l1 = v1 - __half2float(b);
    return ((unsigned)__half_as_ushort(b) << 16) | __half_as_ushort(a);
}
__device__ __forceinline__ unsigned pack_lo(float l0, float l1) {
    return ((unsigned)__half_as_ushort(__float2half_rn(l1)) << 16)
         | __half_as_ushort(__float2half_rn(l0));
}
__device__ __forceinline__ unsigned pack_h(float v0, float v1) {
    return ((unsigned)__half_as_ushort(__float2half_rn(v1)) << 16)
         | __half_as_ushort(__float2half_rn(v0));
}
__device__ __forceinline__ float hf_lo(unsigned w) {
    return __half2float(__ushort_as_half((unsigned short)(w & 0xffffu)));
}
__device__ __forceinline__ float hf_hi(unsigned w) {
    return __half2float(__ushort_as_half((unsigned short)(w >> 16)));
}

// ================= prologue kernels =================
__global__ void rbf_kernel(const float* __restrict__ dist) {
    int idx = blockIdx.x * blockDim.x + threadIdx.x;
    if (idx >= MROWS * GG) return;
    int m = idx / GG, k = idx - m * GG;
    const float delta = 12.0f / 49.0f;
    const float coeff = -0.5f / (delta * delta);
    float t = dist[m] - delta * (float)k;
    d_g[idx] = expf(coeff * t * t);
}

__global__ void bias0_kernel(const float* __restrict__ Win3,
                             const float* __restrict__ bin,
                             const float* __restrict__ rbf_b) {
    int h = blockIdx.x * blockDim.x + threadIdx.x;
    if (h >= HH) return;
    float s = bin[h];
    for (int e = 0; e < EE; e++) s += rbf_b[e] * Win3[(size_t)e * HH + h];
    d_b0[h] = s;
}

#define SBM 64
#define SBN 64
#define SBK 16
__global__ __launch_bounds__(256)
void sgemm64(const float* __restrict__ A, const float* __restrict__ W,
             float* __restrict__ out, int M, int N, int K,
             size_t wstride, size_t ostride)
{
    W += blockIdx.z * wstride;
    out += blockIdx.z * ostride;
    __shared__ float As[SBK][SBM];
    __shared__ float Bs[SBK][SBN];
    int tid = threadIdx.x;
    int tx = tid & 15, ty = tid >> 4;
    int bm = blockIdx.x * SBM, bn = blockIdx.y * SBN;
    float acc[4][4] = {};
    int arow = tid >> 2, acol = (tid & 3) * 4;
    int brow = tid >> 4, bcol = (tid & 15) * 4;
    for (int k0 = 0; k0 < K; k0 += SBK) {
        float4 va = make_float4(0.f, 0.f, 0.f, 0.f);
        if (bm + arow < M) va = *(const float4*)(A + (size_t)(bm + arow) * K + k0 + acol);
        As[acol + 0][arow] = va.x; As[acol + 1][arow] = va.y;
        As[acol + 2][arow] = va.z; As[acol + 3][arow] = va.w;
        *(float4*)&Bs[brow][bcol] = *(const float4*)(W + (size_t)(k0 + brow) * N + bn + bcol);
        __syncthreads();
        #pragma unroll
        for (int kk = 0; kk < SBK; kk++) {
            float a[4], b[4];
            #pragma unroll
            for (int i = 0; i < 4; i++) a[i] = As[kk][ty * 4 + i];
            #pragma unroll
            for (int j = 0; j < 4; j++) b[j] = Bs[kk][tx * 4 + j];
            #pragma unroll
            for (int i = 0; i < 4; i++)
                #pragma unroll
                for (int j = 0; j < 4; j++)
                    acc[i][j] = fmaf(a[i], b[j], acc[i][j]);
        }
        __syncthreads();
    }
    #pragma unroll
    for (int i = 0; i < 4; i++) {
        int row = bm + ty * 4 + i;
        if (row < M)
            #pragma unroll
            for (int j = 0; j < 4; j++)
                out[(size_t)row * N + bn + tx * 4 + j] = acc[i][j];
    }
}

// h0: write gelu(g@Wg + P + Q + b0) as fp16 hi/lo split in FRAGMENT layout
__global__ __launch_bounds__(256)
void h0_kernel(unsigned* __restrict__ oHi, unsigned* __restrict__ oLo)
{
    __shared__ float Gs[64][52];
    __shared__ float Ws[52][64];
    int tid = threadIdx.x;
    int bm = blockIdx.x * 64, bn = blockIdx.y * 64;
    for (int idx = tid; idx < 64 * GG; idx += 256) {
        int r = idx / GG, k = idx - r * GG;
        Gs[r][k] = d_g[(size_t)(bm + r) * GG + k];
    }
    for (int idx = tid; idx < GG * 64; idx += 256) {
        int k = idx >> 6, n = idx & 63;
        Ws[k][n] = d_Wg[k * HH + bn + n];
    }
    __syncthreads();
    int tx = tid & 15, ty = tid >> 4;
    float acc[4][4] = {};
    #pragma unroll 10
    for (int k = 0; k < GG; k++) {
        float a[4], b[4];
        #pragma unroll
        for (int i = 0; i < 4; i++) a[i] = Gs[ty * 4 + i][k];
        #pragma unroll
        for (int j = 0; j < 4; j++) b[j] = Ws[k][tx * 4 + j];
        #pragma unroll
        for (int i = 0; i < 4; i++)
            #pragma unroll
            for (int j = 0; j < 4; j++)
                acc[i][j] = fmaf(a[i], b[j], acc[i][j]);
    }
    const float* P = d_PQ;
    const float* Q = d_PQ + NA * NB * HH;
    #pragma unroll
    for (int i = 0; i < 4; i++) {
        int m = bm + ty * 4 + i;
        int bb = m & (NB - 1);
        int jat = (m / NB) & (NA - 1);
        int iat = m / (NB * NA);
        int col0 = bn + tx * 4;
        float v[4];
        #pragma unroll
        for (int j = 0; j < 4; j++) {
            int col = col0 + j;
            float t = acc[i][j] + P[(iat * NB + bb) * HH + col]
                    + Q[(jat * NB + bb) * HH + col] + d_b0[col];
            v[j] = gelu_exact(t);
        }
        int inrow = m & 15;
        #pragma unroll
        for (int jp = 0; jp < 2; jp++) {
            int col = col0 + jp * 2;
            unsigned off = (unsigned)(((inrow & 7) * 4 + ((col >> 1) & 3)) * 4
                         + ((inrow >> 3) & 1) + (((col >> 3) & 1) << 1));
            size_t idx = FIDX(m >> 4, col >> 4) + off;
            float l0, l1;
            unsigned hw = pack_hi(v[jp * 2], v[jp * 2 + 1], l0, l1);
            oHi[idx] = hw;
            oLo[idx] = pack_lo(l0, l1);
        }
    }
}

// weight prep: W[K][N] fp32 -> Wt[N][K] single fp16 (u32 k-pairs)
__global__ __launch_bounds__(256)
void prep_w(const float* __restrict__ We, const float* __restrict__ Wf,
            unsigned* __restrict__ wt)
{
    __shared__ float ts[64][33];
    int z = blockIdx.z;
    const float* W = (z < 3) ? We + (size_t)z * HH * HH : Wf + (size_t)(z - 3) * HH * HH;
    int k0 = blockIdx.x * 64, n0 = blockIdx.y * 32;
    int tid = threadIdx.x;
    #pragma unroll
    for (int i = 0; i < 8; i++) {
        int r = (tid >> 5) + i * 8, c = tid & 31;
        ts[r][c] = W[(size_t)(k0 + r) * HH + n0 + c];
    }
    __syncthreads();
    size_t zo = (size_t)z * WW;
    #pragma unroll
    for (int i = 0; i < 4; i++) {
        int on = (tid >> 5) + i * 8;
        int ok = tid & 31;
        float v0 = ts[ok * 2][on], v1 = ts[ok * 2 + 1][on];
        size_t oidx = zo + (size_t)(n0 + on) * (HH / 2) + (k0 >> 1) + ok;
        wt[oidx] = pack_h(v0, v1);
    }
}

// ========= fp16 2-pass mma GEMM layer: A-from-gmem fragments, BK=64 chunks =========
// next = res + gelu((Ah+Al)@W^T + bias); res reconstructed from Ah/Al fragments.
// CTA tile 128x128, 256 threads = 8 warps (4m x 2n), warp tile 32x64.
// B: 64-wide k stages (18KB) x3, single __syncthreads per chunk (CUTLASS order).
// Last layer: fused partial dot with Wout -> d_part[row*16 + nt_blk*2 + wn].
#define BSTR 144                  // 128B data + 16B pad (conflict-free ldmatrix)
#define STB (128*BSTR)            // 18432 B per stage
#define NCH 16                    // chunks of 64 k
#define DSMEM_BYTES (3*STB)       // 55296

__global__ __launch_bounds__(256, 2)
void mma_layer(const unsigned* __restrict__ AhF, const unsigned* __restrict__ AlF,
               const uint4* __restrict__ Bw,
               const float* __restrict__ bias,
               unsigned* __restrict__ oHi, unsigned* __restrict__ oLo,
               const float* __restrict__ wout, float* __restrict__ part,
               int lastLayer)
{
    extern __shared__ char dsm[];
    __shared__ float s_bias[128];
    __shared__ float s_wout[128];
    unsigned base = smem_u32(dsm);

    int tid = threadIdx.x;
    int nt_blk = blockIdx.x, mt_blk = blockIdx.y;
    if (tid < 128) {
        s_bias[tid] = bias[nt_blk * 128 + tid];
        if (lastLayer) s_wout[tid] = wout[nt_blk * 128 + tid];
    }

    int wid = tid >> 5, lane = tid & 31;
    int wm = wid & 3, wn = wid >> 2;
    int rowtile0 = mt_blk * 8 + wm * 2;

    float acc[2][8][4];
    #pragma unroll
    for (int i = 0; i < 2; i++)
        #pragma unroll
        for (int j = 0; j < 8; j++)
            #pragma unroll
            for (int k = 0; k < 4; k++) acc[i][j][k] = 0.f;

    const uint4* gB = Bw + (size_t)(nt_blk * 128) * 128;  // 128 uint4 per n-row

    // ldmatrix lane addressing for B
    int g = lane >> 3, lr = lane & 7;
    unsigned boff0 = (unsigned)((wn * 64 + (g >> 1) * 8 + lr) * BSTR + (g & 1) * 16);

    int cprow = tid >> 3, cpseg = tid & 7;   // 1024 cp16 per stage / 256 thr = 4 each
    unsigned cpoff0 = (unsigned)(cprow * BSTR + cpseg * 16);

    // issue B chunks 0 and 1
    #pragma unroll
    for (int pc = 0; pc < 2; pc++) {
        unsigned sb = base + pc * STB;
        #pragma unroll
        for (int p = 0; p < 4; p++) {
            int row = cprow + p * 32;
            cp16(sb + cpoff0 + (unsigned)(p * 32 * BSTR),
                 gB + (size_t)row * 128 + pc * 8 + cpseg);
        }
        asm volatile("cp.async.commit_group;");
    }

    int stage = 0;
    for (int c = 0; c < NCH; c++) {
        if (c + 2 < NCH) asm volatile("cp.async.wait_group 1;");
        else             asm volatile("cp.async.wait_group 0;");
        __syncthreads();
        if (c + 2 < NCH) {
            int ps = stage + 2; if (ps >= 3) ps -= 3;
            unsigned sb = base + ps * STB;
            #pragma unroll
            for (int p = 0; p < 4; p++) {
                int row = cprow + p * 32;
                cp16(sb + cpoff0 + (unsigned)(p * 32 * BSTR),
                     gB + (size_t)row * 128 + (c + 2) * 8 + cpseg);
            }
            asm volatile("cp.async.commit_group;");
        }

        unsigned bb = base + stage * STB;
        #pragma unroll
        for (int kt4 = 0; kt4 < 4; kt4++) {
            int kt = c * 4 + kt4;
            uint4 ah[2], al[2];
            #pragma unroll
            for (int mt = 0; mt < 2; mt++) {
                size_t ai = FIDX(rowtile0 + mt, kt) + lane * 4;
                ah[mt] = *(const uint4*)(AhF + ai);
                al[mt] = *(const uint4*)(AlF + ai);
            }
            unsigned b[4][4];
            unsigned kkb = (unsigned)(kt4 * 32);
            #pragma unroll
            for (int p = 0; p < 4; p++)
                ldsm4(bb + boff0 + kkb + p * (16 * BSTR), b[p]);
            #pragma unroll
            for (int mt = 0; mt < 2; mt++)
                #pragma unroll
                for (int nt = 0; nt < 8; nt++)
                    mma16816(acc[mt][nt], (const unsigned*)&ah[mt],
                             b[nt >> 1][(nt & 1) * 2], b[nt >> 1][(nt & 1) * 2 + 1]);
            #pragma unroll
            for (int mt = 0; mt < 2; mt++)
                #pragma unroll
                for (int nt = 0; nt < 8; nt++)
                    mma16816(acc[mt][nt], (const unsigned*)&al[mt],
                             b[nt >> 1][(nt & 1) * 2], b[nt >> 1][(nt & 1) * 2 + 1]);
        }
        stage++; if (stage == 3) stage = 0;
    }

    // ===== epilogue (fragment-major in AND out) =====
    #pragma unroll
    for (int mt = 0; mt < 2; mt++) {
        float pd0 = 0.f, pd1 = 0.f;   // last-layer dots for half0/half1 rows
        #pragma unroll
        for (int t = 0; t < 4; t++) {
            int kt_out = nt_blk * 8 + wn * 4 + t;
            size_t idx = FIDX(rowtile0 + mt, kt_out) + lane * 4;
            uint4 hw4 = *(const uint4*)(AhF + idx);
            uint4 lw4 = *(const uint4*)(AlF + idx);
            int cl = wn * 64 + t * 16 + (lane & 3) * 2;

            // x: half0, nt=2t | y: half1, nt=2t | z: half0, nt=2t+1 | w: half1, nt=2t+1
            float vx0 = hf_lo(hw4.x) + hf_lo(lw4.x) + gelu_exact(acc[mt][2*t][0] + s_bias[cl]);
            float vx1 = hf_hi(hw4.x) + hf_hi(lw4.x) + gelu_exact(acc[mt][2*t][1] + s_bias[cl + 1]);
            float vy0 = hf_lo(hw4.y) + hf_lo(lw4.y) + gelu_exact(acc[mt][2*t][2] + s_bias[cl]);
            float vy1 = hf_hi(hw4.y) + hf_hi(lw4.y) + gelu_exact(acc[mt][2*t][3] + s_bias[cl + 1]);
            float vz0 = hf_lo(hw4.z) + hf_lo(lw4.z) + gelu_exact(acc[mt][2*t+1][0] + s_bias[cl + 8]);
            float vz1 = hf_hi(hw4.z) + hf_hi(lw4.z) + gelu_exact(acc[mt][2*t+1][1] + s_bias[cl + 9]);
            float vw0 = hf_lo(hw4.w) + hf_lo(lw4.w) + gelu_exact(acc[mt][2*t+1][2] + s_bias[cl + 8]);
            float vw1 = hf_hi(hw4.w) + hf_hi(lw4.w) + gelu_exact(acc[mt][2*t+1][3] + s_bias[cl + 9]);

            if (lastLayer) {
                pd0 += vx0 * s_wout[cl] + vx1 * s_wout[cl + 1]
                     + vz0 * s_wout[cl + 8] + vz1 * s_wout[cl + 9];
                pd1 += vy0 * s_wout[cl] + vy1 * s_wout[cl + 1]
                     + vw0 * s_wout[cl + 8] + vw1 * s_wout[cl + 9];
            } else {
                float l0, l1;
                uint4 oh, ol;
                oh.x = pack_hi(vx0, vx1, l0, l1); ol.x = pack_lo(l0, l1);
                oh.y = pack_hi(vy0, vy1, l0, l1); ol.y = pack_lo(l0, l1);
                oh.z = pack_hi(vz0, vz1, l0, l1); ol.z = pack_lo(l0, l1);
                oh.w = pack_hi(vw0, vw1, l0, l1); ol.w = pack_lo(l0, l1);
                *(uint4*)(oHi + idx) = oh;
                *(uint4*)(oLo + idx) = ol;
            }
        }
        if (lastLayer) {
            pd0 += __shfl_xor_sync(0xffffffffu, pd0, 1);
            pd0 += __shfl_xor_sync(0xffffffffu, pd0, 2);
            pd1 += __shfl_xor_sync(0xffffffffu, pd1, 1);
            pd1 += __shfl_xor_sync(0xffffffffu, pd1, 2);
            if ((lane & 3) == 0) {
                int row0 = mt_blk * 128 + wm * 32 + mt * 16 + (lane >> 2);
                part[(size_t)row0 * 16 + nt_blk * 2 + wn] = pd0;
                part[(size_t)(row0 + 8) * 16 + nt_blk * 2 + wn] = pd1;
            }
        }
    }
}

// ========= final reduction over partial dots (2MB input, deterministic) =========
__global__ __launch_bounds__(128)
void reduce2(const float* __restrict__ part, const float* __restrict__ bout,
             const int* __restrict__ mask, const float* __restrict__ vec_hat,
             float* __restrict__ out, int mode)
{
    __shared__ float sred[4][4];
    int tid = threadIdx.x;
    int jb = blockIdx.x;
    int j = jb / NB, b = jb % NB;
    int warp = tid >> 5, lane = tid & 31;
    float bo = bout[0];
    bool mj = mask[b * NA + j] != 0;

    int i = tid;   // 0..127 = one atom index each
    size_t m = ((size_t)(i * NA + j)) * NB + b;
    float dot = 0.f;
    #pragma unroll
    for (int t = 0; t < 16; t++) dot += part[m * 16 + t];
    float entry = (mj && mask[b * NA + i] != 0) ? 1.0f : 0.0f;
    float val = (dot + bo) * entry;

    float e = val, fx = 0.f, fy = 0.f, fz = 0.f;
    if (mode == 1) {
        const float* v = vec_hat + m * 3;
        fx = val * v[0]; fy = val * v[1]; fz = val * v[2];
    }
    #pragma unroll
    for (int o = 16; o > 0; o >>= 1) {
        e  += __shfl_xor_sync(0xffffffffu, e,  o);
        fx += __shfl_xor_sync(0xffffffffu, fx, o);
        fy += __shfl_xor_sync(0xffffffffu, fy, o);
        fz += __shfl_xor_sync(0xffffffffu, fz, o);
    }
    if (lane == 0) { sred[warp][0] = e; sred[warp][1] = fx; sred[warp][2] = fy; sred[warp][3] = fz; }
    __syncthreads();
    if (tid == 0) {
        float a0 = 0, a1 = 0, a2 = 0, a3 = 0;
        for (int w = 0; w < 4; w++) { a0 += sred[w][0]; a1 += sred[w][1]; a2 += sred[w][2]; a3 += sred[w][3]; }
        if (mode == 0) d_eP[jb] = a0;
        else {
            int o = 2 + (b * NA + j) * 3;
            out[o + 0] = a1 / 60.0f; out[o + 1] = a2 / 60.0f; out[o + 2] = a3 / 60.0f;
        }
    }
}

__global__ void energy_kernel(float* __restrict__ out) {
    int tid = threadIdx.x;
    int b = tid >> 5, lane = tid & 31;
    if (b >= NB) return;
    float s = 0.f;
    for (int j = lane; j < NA; j += 32) s += d_eP[j * NB + b];
    #pragma unroll
    for (int o = 16; o > 0; o >>= 1) s += __shfl_xor_sync(0xffffffffu, s, o);
    if (lane == 0) out[b] = s / 3600.0f;
}

// ========= launch =========
extern "C" void kernel_launch(void* const* d_in, const int* in_sizes, int n_in,
                              void* d_out, int out_size)
{
    const float* x       = (const float*)d_in[0];
    const float* dist    = (const float*)d_in[1];
    const float* vec_hat = (const float*)d_in[2];
    const int*   mask    = (const int*)d_in[3];   // bool promoted to int32
    const float* rbf_W   = (const float*)d_in[4];
    const float* rbf_b   = (const float*)d_in[5];
    const float* Win[2]  = {(const float*)d_in[6],  (const float*)d_in[12]};
    const float* bin[2]  = {(const float*)d_in[7],  (const float*)d_in[13]};
    const float* Wh[2]   = {(const float*)d_in[8],  (const float*)d_in[14]};
    const float* bh[2]   = {(const float*)d_in[9],  (const float*)d_in[15]};
    const float* Wout[2] = {(const float*)d_in[10], (const float*)d_in[16]};
    const float* bout[2] = {(const float*)d_in[11], (const float*)d_in[17]};
    int L = in_sizes[8] / (HH * HH);
    float* out = (float*)d_out;

    static int attr_set = 0;
    if (!attr_set) {
        cudaFuncSetAttribute(mma_layer, cudaFuncAttributeMaxDynamicSharedMemorySize, DSMEM_BYTES);
        attr_set = 1;
    }

    float *PQ, *Wg, *partp;
    unsigned *fHiA, *fLoA, *fHiB, *fLoB, *Wt;
    cudaGetSymbolAddress((void**)&PQ, d_PQ);
    cudaGetSymbolAddress((void**)&Wg, d_Wg);
    cudaGetSymbolAddress((void**)&partp, d_part);
    cudaGetSymbolAddress((void**)&fHiA, d_fHiA);
    cudaGetSymbolAddress((void**)&fLoA, d_fLoA);
    cudaGetSymbolAddress((void**)&fHiB, d_fHiB);
    cudaGetSymbolAddress((void**)&fLoB, d_fLoB);
    cudaGetSymbolAddress((void**)&Wt, d_Wt);

    rbf_kernel<<<(MROWS * GG + 255) / 256, 256>>>(dist);
    prep_w<<<dim3(16, 32, 6), 256>>>(Wh[0], Wh[1], Wt);

    for (int mlp = 0; mlp < 2; mlp++) {
        const float* W1 = Win[mlp];
        const float* W3 = Win[mlp] + (size_t)2 * EE * HH;

        // P and Q in one launch (z selects Win row-slice + output half)
        sgemm64<<<dim3(4, 16, 2), 256>>>(x, W1, PQ, NA * NB, HH, EE,
                                         (size_t)EE * HH, (size_t)NA * NB * HH);
        sgemm64<<<dim3(1, 16, 1), 256>>>(rbf_W, W3, Wg, GG, HH, EE, 0, 0);
        bias0_kernel<<<4, 256>>>(W3, bin[mlp], rbf_b);

        h0_kernel<<<dim3(MROWS / 64, HH / 64), 256>>>(fHiA, fLoA);

        unsigned* curHi = fHiA; unsigned* curLo = fLoA;
        unsigned* nxtHi = fHiB; unsigned* nxtLo = fLoB;
        for (int l = 0; l < L; l++) {
            size_t zo = (size_t)(mlp * 3 + l) * WW;
            int last = (l == L - 1) ? 1 : 0;
            mma_layer<<<dim3(HH / 128, MROWS / 128), 256, DSMEM_BYTES>>>(
                curHi, curLo,
                (const uint4*)(Wt + zo),
                bh[mlp] + (size_t)l * HH, nxtHi, nxtLo,
                Wout[mlp], partp, last);
            unsigned* t1 = curHi; curHi = nxtHi; nxtHi = t1;
            unsigned* t2 = curLo; curLo = nxtLo; nxtLo = t2;
        }

        reduce2<<<NA * NB, 128>>>(partp, bout[mlp], mask, vec_hat, out, mlp);
    }

    energy_kernel<<<1, 64>>>(out);
}

// round 16
// speedup vs baseline: 1.2086x; 1.0729x over previous
#include <cuda_runtime.h>
#include <cuda_fp16.h>
#include <math.h>

#define NA 128
#define NB 2
#define EE 512
#define HH 1024
#define GG 50
#define MROWS (NA*NA*NB)          // 32768
#define AW ((size_t)MROWS*HH/2)   // u32 words per fp16 activation array
#define WW ((size_t)HH*HH/2)      // u32 words per fp16 weight matrix
#define KT 64                     // 16-wide k tiles per row (HH/16)
// fragment tile index: 16x16 tile = 128 u32, laid out lane*4 + reg
#define FIDX(rt, kt) ((((size_t)(rt)) * KT + (kt)) * 128)

// -------- device scratch (no allocations allowed) --------
__device__ float d_g[(size_t)MROWS*GG];
__device__ float d_PQ[2*NA*NB*HH];
__device__ float d_Wg[GG*HH];
__device__ float d_b0[HH];
__device__ float d_eP[NA*NB];
__device__ float d_part[(size_t)MROWS*16];     // per-(row, n-tile, col-half) partial dots
__device__ unsigned d_fHiA[AW];
__device__ unsigned d_fLoA[AW];
__device__ unsigned d_fHiB[AW];
__device__ unsigned d_fLoB[AW];
__device__ unsigned d_Wt[6*WW];

// exact GELU via erff (short polynomial) instead of normcdff (erfcf: slow tail
// path with a division). 1+erff cancellation at x<<0 leaves ~1e-7 abs error.
__device__ __forceinline__ float gelu_exact(float x) {
    return 0.5f * x * (1.0f + erff(x * 0.70710678118f));
}

__device__ __forceinline__ unsigned smem_u32(const void* p) {
    unsigned a;
    asm("{ .reg .u64 t; cvta.to.shared.u64 t, %1; cvt.u32.u64 %0, t; }" : "=r"(a) : "l"(p));
    return a;
}
__device__ __forceinline__ void cp16(unsigned saddr, const void* g) {
    asm volatile("cp.async.cg.shared.global [%0], [%1], 16;" :: "r"(saddr), "l"(g));
}
__device__ __forceinline__ void ldsm4(unsigned addr, unsigned* r) {
    asm volatile("ldmatrix.sync.aligned.m8n8.x4.shared.b16 {%0,%1,%2,%3}, [%4];"
                 : "=r"(r[0]), "=r"(r[1]), "=r"(r[2]), "=r"(r[3]) : "r"(addr));
}
__device__ __forceinline__ void mma16816(float* c, const unsigned* a, unsigned b0, unsigned b1) {
    asm volatile("mma.sync.aligned.m16n8k16.row.col.f32.f16.f16.f32 "
                 "{%0,%1,%2,%3}, {%4,%5,%6,%7}, {%8,%9}, {%0,%1,%2,%3};"
                 : "+f"(c[0]), "+f"(c[1]), "+f"(c[2]), "+f"(c[3])
                 : "r"(a[0]), "r"(a[1]), "r"(a[2]), "r"(a[3]), "r"(b0), "r"(b1));
}
__device__ __forceinline__ unsigned pack_hi(float v0, float v1, float& l0, float& l1) {
    __half a = __float2half_rn(v0), b = __float2half_rn(v1);
    l0 = v0 - __half2float(a);
    l1 = v1 - __half2float(b);
    return ((unsigned)__half_as_ushort(b) << 16) | __half_as_ushort(a);
}
__device__ __forceinline__ unsigned pack_lo(float l0, float l1) {
    return ((unsigned)__half_as_ushort(__float2half_rn(l1)) << 16)
         | __half_as_ushort(__float2half_rn(l0));
}
__device__ __forceinline__ unsigned pack_h(float v0, float v1) {
    return ((unsigned)__half_as_ushort(__float2half_rn(v1)) << 16)
         | __half_as_ushort(__float2half_rn(v0));
}
__device__ __forceinline__ float hf_lo(unsigned w) {
    return __half2float(__ushort_as_half((unsigned short)(w & 0xffffu)));
}
__device__ __forceinline__ float hf_hi(unsigned w) {
    return __half2float(__ushort_as_half((unsigned short)(w >> 16)));
}

// ================= prologue kernels =================
__global__ void rbf_kernel(const float* __restrict__ dist) {
    int idx = blockIdx.x * blockDim.x + threadIdx.x;
    if (idx >= MROWS * GG) return;
    int m = idx / GG, k = idx - m * GG;
    const float delta = 12.0f / 49.0f;
    const float coeff = -0.5f / (delta * delta);
    float t = dist[m] - delta * (float)k;
    d_g[idx] = __expf(coeff * t * t);
}

__global__ void bias0_kernel(const float* __restrict__ Win3,
                             const float* __restrict__ bin,
                             const float* __restrict__ rbf_b) {
    int h = blockIdx.x * blockDim.x + threadIdx.x;
    if (h >= HH) return;
    float s = bin[h];
    for (int e = 0; e < EE; e++) s += rbf_b[e] * Win3[(size_t)e * HH + h];
    d_b0[h] = s;
}

#define SBM 64
#define SBN 64
#define SBK 16
__global__ __launch_bounds__(256)
void sgemm64(const float* __restrict__ A, const float* __restrict__ W,
             float* __restrict__ out, int M, int N, int K,
             size_t wstride, size_t ostride)
{
    W += blockIdx.z * wstride;
    out += blockIdx.z * ostride;
    __shared__ float As[SBK][SBM];
    __shared__ float Bs[SBK][SBN];
    int tid = threadIdx.x;
    int tx = tid & 15, ty = tid >> 4;
    int bm = blockIdx.x * SBM, bn = blockIdx.y * SBN;
    float acc[4][4] = {};
    int arow = tid >> 2, acol = (tid & 3) * 4;
    int brow = tid >> 4, bcol = (tid & 15) * 4;
    for (int k0 = 0; k0 < K; k0 += SBK) {
        float4 va = make_float4(0.f, 0.f, 0.f, 0.f);
        if (bm + arow < M) va = *(const float4*)(A + (size_t)(bm + arow) * K + k0 + acol);
        As[acol + 0][arow] = va.x; As[acol + 1][arow] = va.y;
        As[acol + 2][arow] = va.z; As[acol + 3][arow] = va.w;
        *(float4*)&Bs[brow][bcol] = *(const float4*)(W + (size_t)(k0 + brow) * N + bn + bcol);
        __syncthreads();
        #pragma unroll
        for (int kk = 0; kk < SBK; kk++) {
            float a[4], b[4];
            #pragma unroll
            for (int i = 0; i < 4; i++) a[i] = As[kk][ty * 4 + i];
            #pragma unroll
            for (int j = 0; j < 4; j++) b[j] = Bs[kk][tx * 4 + j];
            #pragma unroll
            for (int i = 0; i < 4; i++)
                #pragma unroll
                for (int j = 0; j < 4; j++)
                    acc[i][j] = fmaf(a[i], b[j], acc[i][j]);
        }
        __syncthreads();
    }
    #pragma unroll
    for (int i = 0; i < 4; i++) {
        int row = bm + ty * 4 + i;
        if (row < M)
            #pragma unroll
            for (int j = 0; j < 4; j++)
                out[(size_t)row * N + bn + tx * 4 + j] = acc[i][j];
    }
}

// h0: write gelu(g@Wg + P + Q + b0) as fp16 hi/lo split in FRAGMENT layout
__global__ __launch_bounds__(256)
void h0_kernel(unsigned* __restrict__ oHi, unsigned* __restrict__ oLo)
{
    __shared__ float Gs[64][52];
    __shared__ float Ws[52][64];
    int tid = threadIdx.x;
    int bm = blockIdx.x * 64, bn = blockIdx.y * 64;
    for (int idx = tid; idx < 64 * GG; idx += 256) {
        int r = idx / GG, k = idx - r * GG;
        Gs[r][k] = d_g[(size_t)(bm + r) * GG + k];
    }
    for (int idx = tid; idx < GG * 64; idx += 256) {
        int k = idx >> 6, n = idx & 63;
        Ws[k][n] = d_Wg[k * HH + bn + n];
    }
    __syncthreads();
    int tx = tid & 15, ty = tid >> 4;
    float acc[4][4] = {};
    #pragma unroll 10
    for (int k = 0; k < GG; k++) {
        float a[4], b[4];
        #pragma unroll
        for (int i = 0; i < 4; i++) a[i] = Gs[ty * 4 + i][k];
        #pragma unroll
        for (int j = 0; j < 4; j++) b[j] = Ws[k][tx * 4 + j];
        #pragma unroll
        for (int i = 0; i < 4; i++)
            #pragma unroll
            for (int j = 0; j < 4; j++)
                acc[i][j] = fmaf(a[i], b[j], acc[i][j]);
    }
    const float* P = d_PQ;
    const float* Q = d_PQ + NA * NB * HH;
    #pragma unroll
    for (int i = 0; i < 4; i++) {
        int m = bm + ty * 4 + i;
        int bb = m & (NB - 1);
        int jat = (m / NB) & (NA - 1);
        int iat = m / (NB * NA);
        int col0 = bn + tx * 4;
        float v[4];
        #pragma unroll
        for (int j = 0; j < 4; j++) {
            int col = col0 + j;
            float t = acc[i][j] + P[(iat * NB + bb) * HH + col]
                    + Q[(jat * NB + bb) * HH + col] + d_b0[col];
            v[j] = gelu_exact(t);
        }
        int inrow = m & 15;
        #pragma unroll
        for (int jp = 0; jp < 2; jp++) {
            int col = col0 + jp * 2;
            unsigned off = (unsigned)(((inrow & 7) * 4 + ((col >> 1) & 3)) * 4
                         + ((inrow >> 3) & 1) + (((col >> 3) & 1) << 1));
            size_t idx = FIDX(m >> 4, col >> 4) + off;
            float l0, l1;
            unsigned hw = pack_hi(v[jp * 2], v[jp * 2 + 1], l0, l1);
            oHi[idx] = hw;
            oLo[idx] = pack_lo(l0, l1);
        }
    }
}

// weight prep: W[K][N] fp32 -> Wt[N][K] single fp16 (u32 k-pairs)
__global__ __launch_bounds__(256)
void prep_w(const float* __restrict__ We, const float* __restrict__ Wf,
            unsigned* __restrict__ wt)
{
    __shared__ float ts[64][33];
    int z = blockIdx.z;
    const float* W = (z < 3) ? We + (size_t)z * HH * HH : Wf + (size_t)(z - 3) * HH * HH;
    int k0 = blockIdx.x * 64, n0 = blockIdx.y * 32;
    int tid = threadIdx.x;
    #pragma unroll
    for (int i = 0; i < 8; i++) {
        int r = (tid >> 5) + i * 8, c = tid & 31;
        ts[r][c] = W[(size_t)(k0 + r) * HH + n0 + c];
    }
    __syncthreads();
    size_t zo = (size_t)z * WW;
    #pragma unroll
    for (int i = 0; i < 4; i++) {
        int on = (tid >> 5) + i * 8;
        int ok = tid & 31;
        float v0 = ts[ok * 2][on], v1 = ts[ok * 2 + 1][on];
        size_t oidx = zo + (size_t)(n0 + on) * (HH / 2) + (k0 >> 1) + ok;
        wt[oidx] = pack_h(v0, v1);
    }
}

// ========= fp16 2-pass mma GEMM layer: A-from-gmem fragments, BK=64 chunks =========
// next = res + gelu((Ah+Al)@W^T + bias); res reconstructed from Ah/Al fragments.
// CTA tile 128x128, 256 threads = 8 warps (4m x 2n), warp tile 32x64.
// B: 64-wide k stages (18KB) x3, single __syncthreads per chunk (CUTLASS order).
// Last layer: fused partial dot with Wout -> d_part[row*16 + nt_blk*2 + wn].
#define BSTR 144                  // 128B data + 16B pad (conflict-free ldmatrix)
#define STB (128*BSTR)            // 18432 B per stage
#define NCH 16                    // chunks of 64 k
#define DSMEM_BYTES (3*STB)       // 55296

__global__ __launch_bounds__(256, 2)
void mma_layer(const unsigned* __restrict__ AhF, const unsigned* __restrict__ AlF,
               const uint4* __restrict__ Bw,
               const float* __restrict__ bias,
               unsigned* __restrict__ oHi, unsigned* __restrict__ oLo,
               const float* __restrict__ wout, float* __restrict__ part,
               int lastLayer)
{
    extern __shared__ char dsm[];
    __shared__ float s_bias[128];
    __shared__ float s_wout[128];
    unsigned base = smem_u32(dsm);

    int tid = threadIdx.x;
    int nt_blk = blockIdx.x, mt_blk = blockIdx.y;
    if (tid < 128) {
        s_bias[tid] = bias[nt_blk * 128 + tid];
        if (lastLayer) s_wout[tid] = wout[nt_blk * 128 + tid];
    }

    int wid = tid >> 5, lane = tid & 31;
    int wm = wid & 3, wn = wid >> 2;
    int rowtile0 = mt_blk * 8 + wm * 2;

    float acc[2][8][4];
    #pragma unroll
    for (int i = 0; i < 2; i++)
        #pragma unroll
        for (int j = 0; j < 8; j++)
            #pragma unroll
            for (int k = 0; k < 4; k++) acc[i][j][k] = 0.f;

    const uint4* gB = Bw + (size_t)(nt_blk * 128) * 128;  // 128 uint4 per n-row

    // ldmatrix lane addressing for B
    int g = lane >> 3, lr = lane & 7;
    unsigned boff0 = (unsigned)((wn * 64 + (g >> 1) * 8 + lr) * BSTR + (g & 1) * 16);

    int cprow = tid >> 3, cpseg = tid & 7;   // 1024 cp16 per stage / 256 thr = 4 each
    unsigned cpoff0 = (unsigned)(cprow * BSTR + cpseg * 16);

    // issue B chunks 0 and 1
    #pragma unroll
    for (int pc = 0; pc < 2; pc++) {
        unsigned sb = base + pc * STB;
        #pragma unroll
        for (int p = 0; p < 4; p++) {
            int row = cprow + p * 32;
            cp16(sb + cpoff0 + (unsigned)(p * 32 * BSTR),
                 gB + (size_t)row * 128 + pc * 8 + cpseg);
        }
        asm volatile("cp.async.commit_group;");
    }

    int stage = 0;
    for (int c = 0; c < NCH; c++) {
        if (c + 2 < NCH) asm volatile("cp.async.wait_group 1;");
        else             asm volatile("cp.async.wait_group 0;");
        __syncthreads();
        if (c + 2 < NCH) {
            int ps = stage + 2; if (ps >= 3) ps -= 3;
            unsigned sb = base + ps * STB;
            #pragma unroll
            for (int p = 0; p < 4; p++) {
                int row = cprow + p * 32;
                cp16(sb + cpoff0 + (unsigned)(p * 32 * BSTR),
                     gB + (size_t)row * 128 + (c + 2) * 8 + cpseg);
            }
            asm volatile("cp.async.commit_group;");
        }

        unsigned bb = base + stage * STB;
        #pragma unroll
        for (int kt4 = 0; kt4 < 4; kt4++) {
            int kt = c * 4 + kt4;
            uint4 ah[2], al[2];
            #pragma unroll
            for (int mt = 0; mt < 2; mt++) {
                size_t ai = FIDX(rowtile0 + mt, kt) + lane * 4;
                ah[mt] = *(const uint4*)(AhF + ai);
                al[mt] = *(const uint4*)(AlF + ai);
            }
            unsigned b[4][4];
            unsigned kkb = (unsigned)(kt4 * 32);
            #pragma unroll
            for (int p = 0; p < 4; p++)
                ldsm4(bb + boff0 + kkb + p * (16 * BSTR), b[p]);
            #pragma unroll
            for (int mt = 0; mt < 2; mt++)
                #pragma unroll
                for (int nt = 0; nt < 8; nt++)
                    mma16816(acc[mt][nt], (const unsigned*)&ah[mt],
                             b[nt >> 1][(nt & 1) * 2], b[nt >> 1][(nt & 1) * 2 + 1]);
            #pragma unroll
            for (int mt = 0; mt < 2; mt++)
                #pragma unroll
                for (int nt = 0; nt < 8; nt++)
                    mma16816(acc[mt][nt], (const unsigned*)&al[mt],
                             b[nt >> 1][(nt & 1) * 2], b[nt >> 1][(nt & 1) * 2 + 1]);
        }
        stage++; if (stage == 3) stage = 0;
    }

    // ===== epilogue (fragment-major in AND out) =====
    #pragma unroll
    for (int mt = 0; mt < 2; mt++) {
        float pd0 = 0.f, pd1 = 0.f;   // last-layer dots for half0/half1 rows
        #pragma unroll
        for (int t = 0; t < 4; t++) {
            int kt_out = nt_blk * 8 + wn * 4 + t;
            size_t idx = FIDX(rowtile0 + mt, kt_out) + lane * 4;
            uint4 hw4 = *(const uint4*)(AhF + idx);
            uint4 lw4 = *(const uint4*)(AlF + idx);
            int cl = wn * 64 + t * 16 + (lane & 3) * 2;

            // x: half0, nt=2t | y: half1, nt=2t | z: half0, nt=2t+1 | w: half1, nt=2t+1
            float vx0 = hf_lo(hw4.x) + hf_lo(lw4.x) + gelu_exact(acc[mt][2*t][0] + s_bias[cl]);
            float vx1 = hf_hi(hw4.x) + hf_hi(lw4.x) + gelu_exact(acc[mt][2*t][1] + s_bias[cl + 1]);
            float vy0 = hf_lo(hw4.y) + hf_lo(lw4.y) + gelu_exact(acc[mt][2*t][2] + s_bias[cl]);
            float vy1 = hf_hi(hw4.y) + hf_hi(lw4.y) + gelu_exact(acc[mt][2*t][3] + s_bias[cl + 1]);
            float vz0 = hf_lo(hw4.z) + hf_lo(lw4.z) + gelu_exact(acc[mt][2*t+1][0] + s_bias[cl + 8]);
            float vz1 = hf_hi(hw4.z) + hf_hi(lw4.z) + gelu_exact(acc[mt][2*t+1][1] + s_bias[cl + 9]);
            float vw0 = hf_lo(hw4.w) + hf_lo(lw4.w) + gelu_exact(acc[mt][2*t+1][2] + s_bias[cl + 8]);
            float vw1 = hf_hi(hw4.w) + hf_hi(lw4.w) + gelu_exact(acc[mt][2*t+1][3] + s_bias[cl + 9]);

            if (lastLayer) {
                pd0 += vx0 * s_wout[cl] + vx1 * s_wout[cl + 1]
                     + vz0 * s_wout[cl + 8] + vz1 * s_wout[cl + 9];
                pd1 += vy0 * s_wout[cl] + vy1 * s_wout[cl + 1]
                     + vw0 * s_wout[cl + 8] + vw1 * s_wout[cl + 9];
            } else {
                float l0, l1;
                uint4 oh, ol;
                oh.x = pack_hi(vx0, vx1, l0, l1); ol.x = pack_lo(l0, l1);
                oh.y = pack_hi(vy0, vy1, l0, l1); ol.y = pack_lo(l0, l1);
                oh.z = pack_hi(vz0, vz1, l0, l1); ol.z = pack_lo(l0, l1);
                oh.w = pack_hi(vw0, vw1, l0, l1); ol.w = pack_lo(l0, l1);
                *(uint4*)(oHi + idx) = oh;
                *(uint4*)(oLo + idx) = ol;
            }
        }
        if (lastLayer) {
            pd0 += __shfl_xor_sync(0xffffffffu, pd0, 1);
            pd0 += __shfl_xor_sync(0xffffffffu, pd0, 2);
            pd1 += __shfl_xor_sync(0xffffffffu, pd1, 1);
            pd1 += __shfl_xor_sync(0xffffffffu, pd1, 2);
            if ((lane & 3) == 0) {
                int row0 = mt_blk * 128 + wm * 32 + mt * 16 + (lane >> 2);
                part[(size_t)row0 * 16 + nt_blk * 2 + wn] = pd0;
                part[(size_t)(row0 + 8) * 16 + nt_blk * 2 + wn] = pd1;
            }
        }
    }
}

// ========= final reduction over partial dots (2MB input, deterministic) =========
__global__ __launch_bounds__(128)
void reduce2(const float* __restrict__ part, const float* __restrict__ bout,
             const int* __restrict__ mask, const float* __restrict__ vec_hat,
             float* __restrict__ out, int mode)
{
    __shared__ float sred[4][4];
    int tid = threadIdx.x;
    int jb = blockIdx.x;
    int j = jb / NB, b = jb % NB;
    int warp = tid >> 5, lane = tid & 31;
    float bo = bout[0];
    bool mj = mask[b * NA + j] != 0;

    int i = tid;   // 0..127 = one atom index each
    size_t m = ((size_t)(i * NA + j)) * NB + b;
    float dot = 0.f;
    #pragma unroll
    for (int t = 0; t < 16; t++) dot += part[m * 16 + t];
    float entry = (mj && mask[b * NA + i] != 0) ? 1.0f : 0.0f;
    float val = (dot + bo) * entry;

    float e = val, fx = 0.f, fy = 0.f, fz = 0.f;
    if (mode == 1) {
        const float* v = vec_hat + m * 3;
        fx = val * v[0]; fy = val * v[1]; fz = val * v[2];
    }
    #pragma unroll
    for (int o = 16; o > 0; o >>= 1) {
        e  += __shfl_xor_sync(0xffffffffu, e,  o);
        fx += __shfl_xor_sync(0xffffffffu, fx, o);
        fy += __shfl_xor_sync(0xffffffffu, fy, o);
        fz += __shfl_xor_sync(0xffffffffu, fz, o);
    }
    if (lane == 0) { sred[warp][0] = e; sred[warp][1] = fx; sred[warp][2] = fy; sred[warp][3] = fz; }
    __syncthreads();
    if (tid == 0) {
        float a0 = 0, a1 = 0, a2 = 0, a3 = 0;
        for (int w = 0; w < 4; w++) { a0 += sred[w][0]; a1 += sred[w][1]; a2 += sred[w][2]; a3 += sred[w][3]; }
        if (mode == 0) d_eP[jb] = a0;
        else {
            int o = 2 + (b * NA + j) * 3;
            out[o + 0] = a1 / 60.0f; out[o + 1] = a2 / 60.0f; out[o + 2] = a3 / 60.0f;
        }
    }
}

__global__ void energy_kernel(float* __restrict__ out) {
    int tid = threadIdx.x;
    int b = tid >> 5, lane = tid & 31;
    if (b >= NB) return;
    float s = 0.f;
    for (int j = lane; j < NA; j += 32) s += d_eP[j * NB + b];
    #pragma unroll
    for (int o = 16; o > 0; o >>= 1) s += __shfl_xor_sync(0xffffffffu, s, o);
    if (lane == 0) out[b] = s / 3600.0f;
}

// ========= launch =========
extern "C" void kernel_launch(void* const* d_in, const int* in_sizes, int n_in,
                              void* d_out, int out_size)
{
    const float* x       = (const float*)d_in[0];
    const float* dist    = (const float*)d_in[1];
    const float* vec_hat = (const float*)d_in[2];
    const int*   mask    = (const int*)d_in[3];   // bool promoted to int32
    const float* rbf_W   = (const float*)d_in[4];
    const float* rbf_b   = (const float*)d_in[5];
    const float* Win[2]  = {(const float*)d_in[6],  (const float*)d_in[12]};
    const float* bin[2]  = {(const float*)d_in[7],  (const float*)d_in[13]};
    const float* Wh[2]   = {(const float*)d_in[8],  (const float*)d_in[14]};
    const float* bh[2]   = {(const float*)d_in[9],  (const float*)d_in[15]};
    const float* Wout[2] = {(const float*)d_in[10], (const float*)d_in[16]};
    const float* bout[2] = {(const float*)d_in[11], (const float*)d_in[17]};
    int L = in_sizes[8] / (HH * HH);
    float* out = (float*)d_out;

    static int attr_set = 0;
    if (!attr_set) {
        cudaFuncSetAttribute(mma_layer, cudaFuncAttributeMaxDynamicSharedMemorySize, DSMEM_BYTES);
        attr_set = 1;
    }

    float *PQ, *Wg, *partp;
    unsigned *fHiA, *fLoA, *fHiB, *fLoB, *Wt;
    cudaGetSymbolAddress((void**)&PQ, d_PQ);
    cudaGetSymbolAddress((void**)&Wg, d_Wg);
    cudaGetSymbolAddress((void**)&partp, d_part);
    cudaGetSymbolAddress((void**)&fHiA, d_fHiA);
    cudaGetSymbolAddress((void**)&fLoA, d_fLoA);
    cudaGetSymbolAddress((void**)&fHiB, d_fHiB);
    cudaGetSymbolAddress((void**)&fLoB, d_fLoB);
    cudaGetSymbolAddress((void**)&Wt, d_Wt);

    rbf_kernel<<<(MROWS * GG + 255) / 256, 256>>>(dist);
    prep_w<<<dim3(16, 32, 6), 256>>>(Wh[0], Wh[1], Wt);

    for (int mlp = 0; mlp < 2; mlp++) {
        const float* W1 = Win[mlp];
        const float* W3 = Win[mlp] + (size_t)2 * EE * HH;

        // P and Q in one launch (z selects Win row-slice + output half)
        sgemm64<<<dim3(4, 16, 2), 256>>>(x, W1, PQ, NA * NB, HH, EE,
                                         (size_t)EE * HH, (size_t)NA * NB * HH);
        sgemm64<<<dim3(1, 16, 1), 256>>>(rbf_W, W3, Wg, GG, HH, EE, 0, 0);
        bias0_kernel<<<4, 256>>>(W3, bin[mlp], rbf_b);

        h0_kernel<<<dim3(MROWS / 64, HH / 64), 256>>>(fHiA, fLoA);

        unsigned* curHi = fHiA; unsigned* curLo = fLoA;
        unsigned* nxtHi = fHiB; unsigned* nxtLo = fLoB;
        for (int l = 0; l < L; l++) {
            size_t zo = (size_t)(mlp * 3 + l) * WW;
            int last = (l == L - 1) ? 1 : 0;
            mma_layer<<<dim3(HH / 128, MROWS / 128), 256, DSMEM_BYTES>>>(
                curHi, curLo,
                (const uint4*)(Wt + zo),
                bh[mlp] + (size_t)l * HH, nxtHi, nxtLo,
                Wout[mlp], partp, last);
            unsigned* t1 = curHi; curHi = nxtHi; nxtHi = t1;
            unsigned* t2 = curLo; curLo = nxtLo; nxtLo = t2;
        }

        reduce2<<<NA * NB, 128>>>(partp, bout[mlp], mask, vec_hat, out, mlp);
    }

    energy_kernel<<<1, 64>>>(out);
}

// round 17
// speedup vs baseline: 1.3197x; 1.0919x over previous
#include <cuda_runtime.h>
#include <cuda_fp16.h>
#include <math.h>

#define NA 128
#define NB 2
#define EE 512
#define HH 1024
#define GG 50
#define MROWS (NA*NA*NB)          // 32768
#define AW ((size_t)MROWS*HH/2)   // u32 words per fp16 activation array
#define WW ((size_t)HH*HH/2)      // u32 words per fp16 weight matrix
#define KT 64                     // 16-wide k tiles per row (HH/16)
// fragment tile index: 16x16 tile = 128 u32, laid out lane*4 + reg
#define FIDX(rt, kt) ((((size_t)(rt)) * KT + (kt)) * 128)

// -------- device scratch (no allocations allowed) --------
__device__ float d_PQ[2*NA*NB*HH];
__device__ float d_Wg[GG*HH];
__device__ float d_b0[HH];
__device__ float d_eP[NA*NB];
__device__ float d_part[(size_t)MROWS*16];     // per-(row, n-tile, col-half) partial dots
__device__ unsigned d_gHi[(size_t)MROWS*32];   // rbf features, fp16 hi, fragment layout (K=64 padded)
__device__ unsigned d_gLo[(size_t)MROWS*32];
__device__ unsigned d_wgt[1024*32];            // Wg fp16 n-major k-pairs (K=64 padded)
__device__ unsigned d_fHiA[AW];
__device__ unsigned d_fLoA[AW];
__device__ unsigned d_fHiB[AW];
__device__ unsigned d_fLoB[AW];
__device__ unsigned d_Wt[6*WW];

// exact GELU via erff (short polynomial; no erfcf division tail)
__device__ __forceinline__ float gelu_exact(float x) {
    return 0.5f * x * (1.0f + erff(x * 0.70710678118f));
}

__device__ __forceinline__ unsigned smem_u32(const void* p) {
    unsigned a;
    asm("{ .reg .u64 t; cvta.to.shared.u64 t, %1; cvt.u32.u64 %0, t; }" : "=r"(a) : "l"(p));
    return a;
}
__device__ __forceinline__ void cp16(unsigned saddr, const void* g) {
    asm volatile("cp.async.cg.shared.global [%0], [%1], 16;" :: "r"(saddr), "l"(g));
}
__device__ __forceinline__ void ldsm4(unsigned addr, unsigned* r) {
    asm volatile("ldmatrix.sync.aligned.m8n8.x4.shared.b16 {%0,%1,%2,%3}, [%4];"
                 : "=r"(r[0]), "=r"(r[1]), "=r"(r[2]), "=r"(r[3]) : "r"(addr));
}
__device__ __forceinline__ void mma16816(float* c, const unsigned* a, unsigned b0, unsigned b1) {
    asm volatile("mma.sync.aligned.m16n8k16.row.col.f32.f16.f16.f32 "
                 "{%0,%1,%2,%3}, {%4,%5,%6,%7}, {%8,%9}, {%0,%1,%2,%3};"
                 : "+f"(c[0]), "+f"(c[1]), "+f"(c[2]), "+f"(c[3])
                 : "r"(a[0]), "r"(a[1]), "r"(a[2]), "r"(a[3]), "r"(b0), "r"(b1));
}
__device__ __forceinline__ unsigned pack_hi(float v0, float v1, float& l0, float& l1) {
    __half a = __float2half_rn(v0), b = __float2half_rn(v1);
    l0 = v0 - __half2float(a);
    l1 = v1 - __half2float(b);
    return ((unsigned)__half_as_ushort(b) << 16) | __half_as_ushort(a);
}
__device__ __forceinline__ unsigned pack_lo(float l0, float l1) {
    return ((unsigned)__half_as_ushort(__float2half_rn(l1)) << 16)
         | __half_as_ushort(__float2half_rn(l0));
}
__device__ __forceinline__ unsigned pack_h(float v0, float v1) {
    return ((unsigned)__half_as_ushort(__float2half_rn(v1)) << 16)
         | __half_as_ushort(__float2half_rn(v0));
}
__device__ __forceinline__ float hf_lo(unsigned w) {
    return __half2float(__ushort_as_half((unsigned short)(w & 0xffffu)));
}
__device__ __forceinline__ float hf_hi(unsigned w) {
    return __half2float(__ushort_as_half((unsigned short)(w >> 16)));
}

// ================= prologue kernels =================
// rbf2: Gaussian features straight into fp16 hi/lo A-fragment layout, K padded to 64
__global__ void rbf2_kernel(const float* __restrict__ dist) {
    int idx = blockIdx.x * blockDim.x + threadIdx.x;
    if (idx >= MROWS * 32) return;
    int m = idx >> 5, kp = idx & 31;
    int k0 = kp * 2;
    float d = dist[m];
    const float delta = 12.0f / 49.0f;
    const float coeff = -0.5f / (delta * delta);
    float t0 = d - delta * (float)k0;
    float t1 = d - delta * (float)(k0 + 1);
    float g0 = (k0 < GG) ? __expf(coeff * t0 * t0) : 0.f;
    float g1 = (k0 + 1 < GG) ? __expf(coeff * t1 * t1) : 0.f;
    int inrow = m & 15;
    unsigned off = (unsigned)((((inrow & 7) * 4 + ((k0 >> 1) & 3)) * 4)
                 + ((inrow >> 3) & 1) + (((k0 >> 3) & 1) << 1));
    size_t o = (size_t)(m >> 4) * 512 + (size_t)(k0 >> 4) * 128 + off;
    float l0, l1;
    d_gHi[o] = pack_hi(g0, g1, l0, l1);
    d_gLo[o] = pack_lo(l0, l1);
}

__global__ void bias0_kernel(const float* __restrict__ Win3,
                             const float* __restrict__ bin,
                             const float* __restrict__ rbf_b) {
    int h = blockIdx.x * blockDim.x + threadIdx.x;
    if (h >= HH) return;
    float s = bin[h];
    for (int e = 0; e < EE; e++) s += rbf_b[e] * Win3[(size_t)e * HH + h];
    d_b0[h] = s;
}

// pack Wg fp32 [GG][HH] -> fp16 n-major k-pairs, K padded to 64
__global__ void pack_wg_kernel(unsigned* __restrict__ wgt) {
    int idx = blockIdx.x * blockDim.x + threadIdx.x;
    if (idx >= 1024 * 32) return;
    int n = idx >> 5, kp = idx & 31;
    int k0 = kp * 2;
    float v0 = (k0 < GG) ? d_Wg[(size_t)k0 * HH + n] : 0.f;
    float v1 = (k0 + 1 < GG) ? d_Wg[(size_t)(k0 + 1) * HH + n] : 0.f;
    wgt[n * 32 + kp] = pack_h(v0, v1);
}

#define SBM 64
#define SBN 64
#define SBK 16
__global__ __launch_bounds__(256)
void sgemm64(const float* __restrict__ A, const float* __restrict__ W,
             float* __restrict__ out, int M, int N, int K,
             size_t wstride, size_t ostride)
{
    W += blockIdx.z * wstride;
    out += blockIdx.z * ostride;
    __shared__ float As[SBK][SBM];
    __shared__ float Bs[SBK][SBN];
    int tid = threadIdx.x;
    int tx = tid & 15, ty = tid >> 4;
    int bm = blockIdx.x * SBM, bn = blockIdx.y * SBN;
    float acc[4][4] = {};
    int arow = tid >> 2, acol = (tid & 3) * 4;
    int brow = tid >> 4, bcol = (tid & 15) * 4;
    for (int k0 = 0; k0 < K; k0 += SBK) {
        float4 va = make_float4(0.f, 0.f, 0.f, 0.f);
        if (bm + arow < M) va = *(const float4*)(A + (size_t)(bm + arow) * K + k0 + acol);
        As[acol + 0][arow] = va.x; As[acol + 1][arow] = va.y;
        As[acol + 2][arow] = va.z; As[acol + 3][arow] = va.w;
        *(float4*)&Bs[brow][bcol] = *(const float4*)(W + (size_t)(k0 + brow) * N + bn + bcol);
        __syncthreads();
        #pragma unroll
        for (int kk = 0; kk < SBK; kk++) {
            float a[4], b[4];
            #pragma unroll
            for (int i = 0; i < 4; i++) a[i] = As[kk][ty * 4 + i];
            #pragma unroll
            for (int j = 0; j < 4; j++) b[j] = Bs[kk][tx * 4 + j];
            #pragma unroll
            for (int i = 0; i < 4; i++)
                #pragma unroll
                for (int j = 0; j < 4; j++)
                    acc[i][j] = fmaf(a[i], b[j], acc[i][j]);
        }
        __syncthreads();
    }
    #pragma unroll
    for (int i = 0; i < 4; i++) {
        int row = bm + ty * 4 + i;
        if (row < M)
            #pragma unroll
            for (int j = 0; j < 4; j++)
                out[(size_t)row * N + bn + tx * 4 + j] = acc[i][j];
    }
}

// ========= h0 via tensor cores: gelu(g@Wg + P + Q + b0) -> fragment hi/lo =========
// CTA 128x128, 256 thr = 8 warps (4m x 2n), single K=64 chunk (B tile in smem once).
#define H0BSTR 144
__global__ __launch_bounds__(256, 2)
void h0_mma(const unsigned* __restrict__ gHi, const unsigned* __restrict__ gLo,
            const uint4* __restrict__ Wgt,
            unsigned* __restrict__ oHi, unsigned* __restrict__ oLo)
{
    __shared__ char sB[128 * H0BSTR];
    __shared__ float s_b0[128];
    __shared__ float s_P[2][128];
    unsigned base = smem_u32(sB);

    int tid = threadIdx.x;
    int nt_blk = blockIdx.x, mt_blk = blockIdx.y;
    int iat = mt_blk >> 1;
    if (tid < 128) s_b0[tid] = d_b0[nt_blk * 128 + tid];
    else {
        int c = tid - 128;
        s_P[0][c] = d_PQ[(size_t)(iat * 2 + 0) * HH + nt_blk * 128 + c];
        s_P[1][c] = d_PQ[(size_t)(iat * 2 + 1) * HH + nt_blk * 128 + c];
    }

    // load B tile: 128 n-rows x 8 uint4 (64 fp16 k)
    {
        int cprow = tid >> 3, cpseg = tid & 7;
        unsigned cpoff = (unsigned)(cprow * H0BSTR + cpseg * 16);
        #pragma unroll
        for (int p = 0; p < 4; p++) {
            int row = cprow + p * 32;
            cp16(base + cpoff + (unsigned)(p * 32 * H0BSTR),
                 Wgt + (size_t)(nt_blk * 128 + row) * 8 + cpseg);
        }
        asm volatile("cp.async.commit_group;");
    }

    int wid = tid >> 5, lane = tid & 31;
    int wm = wid & 3, wn = wid >> 2;
    int rowtile0 = mt_blk * 8 + wm * 2;

    float acc[2][8][4];
    #pragma unroll
    for (int i = 0; i < 2; i++)
        #pragma unroll
        for (int j = 0; j < 8; j++)
            #pragma unroll
            for (int k = 0; k < 4; k++) acc[i][j][k] = 0.f;

    int g = lane >> 3, lr = lane & 7;
    unsigned boff0 = (unsigned)((wn * 64 + (g >> 1) * 8 + lr) * H0BSTR + (g & 1) * 16);

    asm volatile("cp.async.wait_group 0;");
    __syncthreads();

    #pragma unroll
    for (int kt = 0; kt < 4; kt++) {
        uint4 ah[2], al[2];
        #pragma unroll
        for (int mt = 0; mt < 2; mt++) {
            size_t ai = (size_t)(rowtile0 + mt) * 512 + (size_t)kt * 128 + lane * 4;
            ah[mt] = *(const uint4*)(gHi + ai);
            al[mt] = *(const uint4*)(gLo + ai);
        }
        unsigned b[4][4];
        unsigned kkb = (unsigned)(kt * 32);
        #pragma unroll
        for (int p = 0; p < 4; p++)
            ldsm4(base + boff0 + kkb + p * (16 * H0BSTR), b[p]);
        #pragma unroll
        for (int mt = 0; mt < 2; mt++)
            #pragma unroll
            for (int nt = 0; nt < 8; nt++)
                mma16816(acc[mt][nt], (const unsigned*)&ah[mt],
                         b[nt >> 1][(nt & 1) * 2], b[nt >> 1][(nt & 1) * 2 + 1]);
        #pragma unroll
        for (int mt = 0; mt < 2; mt++)
            #pragma unroll
            for (int nt = 0; nt < 8; nt++)
                mma16816(acc[mt][nt], (const unsigned*)&al[mt],
                         b[nt >> 1][(nt & 1) * 2], b[nt >> 1][(nt & 1) * 2 + 1]);
    }
    __syncthreads();

    // epilogue: + P + Q + b0, gelu, fragment hi/lo out
    const float* Qp = d_PQ + (size_t)NA * NB * HH;
    #pragma unroll
    for (int mt = 0; mt < 2; mt++) {
        int m0 = mt_blk * 128 + wm * 32 + mt * 16 + (lane >> 2);
        int m1 = m0 + 8;
        int bb = m0 & 1;
        size_t q0row = (size_t)(((m0 >> 1) & 127) * 2 + bb) * HH;
        size_t q1row = (size_t)(((m1 >> 1) & 127) * 2 + bb) * HH;
        #pragma unroll
        for (int t = 0; t < 4; t++) {
            int kt_out = nt_blk * 8 + wn * 4 + t;
            size_t idx = FIDX(rowtile0 + mt, kt_out) + lane * 4;
            int cl = wn * 64 + t * 16 + (lane & 3) * 2;
            int col = nt_blk * 128 + cl;

            float2 qx = *(const float2*)(Qp + q0row + col);
            float2 qy = *(const float2*)(Qp + q1row + col);
            float2 qz = *(const float2*)(Qp + q0row + col + 8);
            float2 qw = *(const float2*)(Qp + q1row + col + 8);

            float vx0 = gelu_exact(acc[mt][2*t][0] + s_b0[cl]     + s_P[bb][cl]     + qx.x);
            float vx1 = gelu_exact(acc[mt][2*t][1] + s_b0[cl + 1] + s_P[bb][cl + 1] + qx.y);
            float vy0 = gelu_exact(acc[mt][2*t][2] + s_b0[cl]     + s_P[bb][cl]     + qy.x);
            float vy1 = gelu_exact(acc[mt][2*t][3] + s_b0[cl + 1] + s_P[bb][cl + 1] + qy.y);
            float vz0 = gelu_exact(acc[mt][2*t+1][0] + s_b0[cl + 8] + s_P[bb][cl + 8] + qz.x);
            float vz1 = gelu_exact(acc[mt][2*t+1][1] + s_b0[cl + 9] + s_P[bb][cl + 9] + qz.y);
            float vw0 = gelu_exact(acc[mt][2*t+1][2] + s_b0[cl + 8] + s_P[bb][cl + 8] + qw.x);
            float vw1 = gelu_exact(acc[mt][2*t+1][3] + s_b0[cl + 9] + s_P[bb][cl + 9] + qw.y);

            float l0, l1;
            uint4 oh, ol;
            oh.x = pack_hi(vx0, vx1, l0, l1); ol.x = pack_lo(l0, l1);
            oh.y = pack_hi(vy0, vy1, l0, l1); ol.y = pack_lo(l0, l1);
            oh.z = pack_hi(vz0, vz1, l0, l1); ol.z = pack_lo(l0, l1);
            oh.w = pack_hi(vw0, vw1, l0, l1); ol.w = pack_lo(l0, l1);
            *(uint4*)(oHi + idx) = oh;
            *(uint4*)(oLo + idx) = ol;
        }
    }
}

// weight prep: W[K][N] fp32 -> Wt[N][K] single fp16 (u32 k-pairs)
__global__ __launch_bounds__(256)
void prep_w(const float* __restrict__ We, const float* __restrict__ Wf,
            unsigned* __restrict__ wt)
{
    __shared__ float ts[64][33];
    int z = blockIdx.z;
    const float* W = (z < 3) ? We + (size_t)z * HH * HH : Wf + (size_t)(z - 3) * HH * HH;
    int k0 = blockIdx.x * 64, n0 = blockIdx.y * 32;
    int tid = threadIdx.x;
    #pragma unroll
    for (int i = 0; i < 8; i++) {
        int r = (tid >> 5) + i * 8, c = tid & 31;
        ts[r][c] = W[(size_t)(k0 + r) * HH + n0 + c];
    }
    __syncthreads();
    size_t zo = (size_t)z * WW;
    #pragma unroll
    for (int i = 0; i < 4; i++) {
        int on = (tid >> 5) + i * 8;
        int ok = tid & 31;
        float v0 = ts[ok * 2][on], v1 = ts[ok * 2 + 1][on];
        size_t oidx = zo + (size_t)(n0 + on) * (HH / 2) + (k0 >> 1) + ok;
        wt[oidx] = pack_h(v0, v1);
    }
}

// ========= fp16 2-pass mma GEMM layer: A-from-gmem fragments, BK=64 chunks =========
#define BSTR 144                  // 128B data + 16B pad (conflict-free ldmatrix)
#define STB (128*BSTR)            // 18432 B per stage
#define NCH 16                    // chunks of 64 k
#define DSMEM_BYTES (3*STB)       // 55296

__global__ __launch_bounds__(256, 2)
void mma_layer(const unsigned* __restrict__ AhF, const unsigned* __restrict__ AlF,
               const uint4* __restrict__ Bw,
               const float* __restrict__ bias,
               unsigned* __restrict__ oHi, unsigned* __restrict__ oLo,
               const float* __restrict__ wout, float* __restrict__ part,
               int lastLayer)
{
    extern __shared__ char dsm[];
    __shared__ float s_bias[128];
    __shared__ float s_wout[128];
    unsigned base = smem_u32(dsm);

    int tid = threadIdx.x;
    int nt_blk = blockIdx.x, mt_blk = blockIdx.y;
    if (tid < 128) {
        s_bias[tid] = bias[nt_blk * 128 + tid];
        if (lastLayer) s_wout[tid] = wout[nt_blk * 128 + tid];
    }

    int wid = tid >> 5, lane = tid & 31;
    int wm = wid & 3, wn = wid >> 2;
    int rowtile0 = mt_blk * 8 + wm * 2;

    float acc[2][8][4];
    #pragma unroll
    for (int i = 0; i < 2; i++)
        #pragma unroll
        for (int j = 0; j < 8; j++)
            #pragma unroll
            for (int k = 0; k < 4; k++) acc[i][j][k] = 0.f;

    const uint4* gB = Bw + (size_t)(nt_blk * 128) * 128;  // 128 uint4 per n-row

    int g = lane >> 3, lr = lane & 7;
    unsigned boff0 = (unsigned)((wn * 64 + (g >> 1) * 8 + lr) * BSTR + (g & 1) * 16);

    int cprow = tid >> 3, cpseg = tid & 7;
    unsigned cpoff0 = (unsigned)(cprow * BSTR + cpseg * 16);

    #pragma unroll
    for (int pc = 0; pc < 2; pc++) {
        unsigned sb = base + pc * STB;
        #pragma unroll
        for (int p = 0; p < 4; p++) {
            int row = cprow + p * 32;
            cp16(sb + cpoff0 + (unsigned)(p * 32 * BSTR),
                 gB + (size_t)row * 128 + pc * 8 + cpseg);
        }
        asm volatile("cp.async.commit_group;");
    }

    int stage = 0;
    for (int c = 0; c < NCH; c++) {
        if (c + 2 < NCH) asm volatile("cp.async.wait_group 1;");
        else             asm volatile("cp.async.wait_group 0;");
        __syncthreads();
        if (c + 2 < NCH) {
            int ps = stage + 2; if (ps >= 3) ps -= 3;
            unsigned sb = base + ps * STB;
            #pragma unroll
            for (int p = 0; p < 4; p++) {
                int row = cprow + p * 32;
                cp16(sb + cpoff0 + (unsigned)(p * 32 * BSTR),
                     gB + (size_t)row * 128 + (c + 2) * 8 + cpseg);
            }
            asm volatile("cp.async.commit_group;");
        }

        unsigned bb = base + stage * STB;
        #pragma unroll
        for (int kt4 = 0; kt4 < 4; kt4++) {
            int kt = c * 4 + kt4;
            uint4 ah[2], al[2];
            #pragma unroll
            for (int mt = 0; mt < 2; mt++) {
                size_t ai = FIDX(rowtile0 + mt, kt) + lane * 4;
                ah[mt] = *(const uint4*)(AhF + ai);
                al[mt] = *(const uint4*)(AlF + ai);
            }
            unsigned b[4][4];
            unsigned kkb = (unsigned)(kt4 * 32);
            #pragma unroll
            for (int p = 0; p < 4; p++)
                ldsm4(bb + boff0 + kkb + p * (16 * BSTR), b[p]);
            #pragma unroll
            for (int mt = 0; mt < 2; mt++)
                #pragma unroll
                for (int nt = 0; nt < 8; nt++)
                    mma16816(acc[mt][nt], (const unsigned*)&ah[mt],
                             b[nt >> 1][(nt & 1) * 2], b[nt >> 1][(nt & 1) * 2 + 1]);
            #pragma unroll
            for (int mt = 0; mt < 2; mt++)
                #pragma unroll
                for (int nt = 0; nt < 8; nt++)
                    mma16816(acc[mt][nt], (const unsigned*)&al[mt],
                             b[nt >> 1][(nt & 1) * 2], b[nt >> 1][(nt & 1) * 2 + 1]);
        }
        stage++; if (stage == 3) stage = 0;
    }

    // ===== epilogue (fragment-major in AND out) =====
    #pragma unroll
    for (int mt = 0; mt < 2; mt++) {
        float pd0 = 0.f, pd1 = 0.f;
        #pragma unroll
        for (int t = 0; t < 4; t++) {
            int kt_out = nt_blk * 8 + wn * 4 + t;
            size_t idx = FIDX(rowtile0 + mt, kt_out) + lane * 4;
            uint4 hw4 = *(const uint4*)(AhF + idx);
            uint4 lw4 = *(const uint4*)(AlF + idx);
            int cl = wn * 64 + t * 16 + (lane & 3) * 2;

            float vx0 = hf_lo(hw4.x) + hf_lo(lw4.x) + gelu_exact(acc[mt][2*t][0] + s_bias[cl]);
            float vx1 = hf_hi(hw4.x) + hf_hi(lw4.x) + gelu_exact(acc[mt][2*t][1] + s_bias[cl + 1]);
            float vy0 = hf_lo(hw4.y) + hf_lo(lw4.y) + gelu_exact(acc[mt][2*t][2] + s_bias[cl]);
            float vy1 = hf_hi(hw4.y) + hf_hi(lw4.y) + gelu_exact(acc[mt][2*t][3] + s_bias[cl + 1]);
            float vz0 = hf_lo(hw4.z) + hf_lo(lw4.z) + gelu_exact(acc[mt][2*t+1][0] + s_bias[cl + 8]);
            float vz1 = hf_hi(hw4.z) + hf_hi(lw4.z) + gelu_exact(acc[mt][2*t+1][1] + s_bias[cl + 9]);
            float vw0 = hf_lo(hw4.w) + hf_lo(lw4.w) + gelu_exact(acc[mt][2*t+1][2] + s_bias[cl + 8]);
            float vw1 = hf_hi(hw4.w) + hf_hi(lw4.w) + gelu_exact(acc[mt][2*t+1][3] + s_bias[cl + 9]);

            if (lastLayer) {
                pd0 += vx0 * s_wout[cl] + vx1 * s_wout[cl + 1]
                     + vz0 * s_wout[cl + 8] + vz1 * s_wout[cl + 9];
                pd1 += vy0 * s_wout[cl] + vy1 * s_wout[cl + 1]
                     + vw0 * s_wout[cl + 8] + vw1 * s_wout[cl + 9];
            } else {
                float l0, l1;
                uint4 oh, ol;
                oh.x = pack_hi(vx0, vx1, l0, l1); ol.x = pack_lo(l0, l1);
                oh.y = pack_hi(vy0, vy1, l0, l1); ol.y = pack_lo(l0, l1);
                oh.z = pack_hi(vz0, vz1, l0, l1); ol.z = pack_lo(l0, l1);
                oh.w = pack_hi(vw0, vw1, l0, l1); ol.w = pack_lo(l0, l1);
                *(uint4*)(oHi + idx) = oh;
                *(uint4*)(oLo + idx) = ol;
            }
        }
        if (lastLayer) {
            pd0 += __shfl_xor_sync(0xffffffffu, pd0, 1);
            pd0 += __shfl_xor_sync(0xffffffffu, pd0, 2);
            pd1 += __shfl_xor_sync(0xffffffffu, pd1, 1);
            pd1 += __shfl_xor_sync(0xffffffffu, pd1, 2);
            if ((lane & 3) == 0) {
                int row0 = mt_blk * 128 + wm * 32 + mt * 16 + (lane >> 2);
                part[(size_t)row0 * 16 + nt_blk * 2 + wn] = pd0;
                part[(size_t)(row0 + 8) * 16 + nt_blk * 2 + wn] = pd1;
            }
        }
    }
}

// ========= final reduction over partial dots (2MB input, deterministic) =========
__global__ __launch_bounds__(128)
void reduce2(const float* __restrict__ part, const float* __restrict__ bout,
             const int* __restrict__ mask, const float* __restrict__ vec_hat,
             float* __restrict__ out, int mode)
{
    __shared__ float sred[4][4];
    int tid = threadIdx.x;
    int jb = blockIdx.x;
    int j = jb / NB, b = jb % NB;
    int warp = tid >> 5, lane = tid & 31;
    float bo = bout[0];
    bool mj = mask[b * NA + j] != 0;

    int i = tid;
    size_t m = ((size_t)(i * NA + j)) * NB + b;
    float dot = 0.f;
    #pragma unroll
    for (int t = 0; t < 16; t++) dot += part[m * 16 + t];
    float entry = (mj && mask[b * NA + i] != 0) ? 1.0f : 0.0f;
    float val = (dot + bo) * entry;

    float e = val, fx = 0.f, fy = 0.f, fz = 0.f;
    if (mode == 1) {
        const float* v = vec_hat + m * 3;
        fx = val * v[0]; fy = val * v[1]; fz = val * v[2];
    }
    #pragma unroll
    for (int o = 16; o > 0; o >>= 1) {
        e  += __shfl_xor_sync(0xffffffffu, e,  o);
        fx += __shfl_xor_sync(0xffffffffu, fx, o);
        fy += __shfl_xor_sync(0xffffffffu, fy, o);
        fz += __shfl_xor_sync(0xffffffffu, fz, o);
    }
    if (lane == 0) { sred[warp][0] = e; sred[warp][1] = fx; sred[warp][2] = fy; sred[warp][3] = fz; }
    __syncthreads();
    if (tid == 0) {
        float a0 = 0, a1 = 0, a2 = 0, a3 = 0;
        for (int w = 0; w < 4; w++) { a0 += sred[w][0]; a1 += sred[w][1]; a2 += sred[w][2]; a3 += sred[w][3]; }
        if (mode == 0) d_eP[jb] = a0;
        else {
            int o = 2 + (b * NA + j) * 3;
            out[o + 0] = a1 / 60.0f; out[o + 1] = a2 / 60.0f; out[o + 2] = a3 / 60.0f;
        }
    }
}

__global__ void energy_kernel(float* __restrict__ out) {
    int tid = threadIdx.x;
    int b = tid >> 5, lane = tid & 31;
    if (b >= NB) return;
    float s = 0.f;
    for (int j = lane; j < NA; j += 32) s += d_eP[j * NB + b];
    #pragma unroll
    for (int o = 16; o > 0; o >>= 1) s += __shfl_xor_sync(0xffffffffu, s, o);
    if (lane == 0) out[b] = s / 3600.0f;
}

// ========= launch =========
extern "C" void kernel_launch(void* const* d_in, const int* in_sizes, int n_in,
                              void* d_out, int out_size)
{
    const float* x       = (const float*)d_in[0];
    const float* dist    = (const float*)d_in[1];
    const float* vec_hat = (const float*)d_in[2];
    const int*   mask    = (const int*)d_in[3];   // bool promoted to int32
    const float* rbf_W   = (const float*)d_in[4];
    const float* rbf_b   = (const float*)d_in[5];
    const float* Win[2]  = {(const float*)d_in[6],  (const float*)d_in[12]};
    const float* bin[2]  = {(const float*)d_in[7],  (const float*)d_in[13]};
    const float* Wh[2]   = {(const float*)d_in[8],  (const float*)d_in[14]};
    const float* bh[2]   = {(const float*)d_in[9],  (const float*)d_in[15]};
    const float* Wout[2] = {(const float*)d_in[10], (const float*)d_in[16]};
    const float* bout[2] = {(const float*)d_in[11], (const float*)d_in[17]};
    int L = in_sizes[8] / (HH * HH);
    float* out = (float*)d_out;

    static int attr_set = 0;
    if (!attr_set) {
        cudaFuncSetAttribute(mma_layer, cudaFuncAttributeMaxDynamicSharedMemorySize, DSMEM_BYTES);
        attr_set = 1;
    }

    float *PQ, *Wg, *partp;
    unsigned *fHiA, *fLoA, *fHiB, *fLoB, *Wt, *gHi, *gLo, *wgt;
    cudaGetSymbolAddress((void**)&PQ, d_PQ);
    cudaGetSymbolAddress((void**)&Wg, d_Wg);
    cudaGetSymbolAddress((void**)&partp, d_part);
    cudaGetSymbolAddress((void**)&fHiA, d_fHiA);
    cudaGetSymbolAddress((void**)&fLoA, d_fLoA);
    cudaGetSymbolAddress((void**)&fHiB, d_fHiB);
    cudaGetSymbolAddress((void**)&fLoB, d_fLoB);
    cudaGetSymbolAddress((void**)&Wt, d_Wt);
    cudaGetSymbolAddress((void**)&gHi, d_gHi);
    cudaGetSymbolAddress((void**)&gLo, d_gLo);
    cudaGetSymbolAddress((void**)&wgt, d_wgt);

    rbf2_kernel<<<(MROWS * 32 + 255) / 256, 256>>>(dist);
    prep_w<<<dim3(16, 32, 6), 256>>>(Wh[0], Wh[1], Wt);

    for (int mlp = 0; mlp < 2; mlp++) {
        const float* W1 = Win[mlp];
        const float* W3 = Win[mlp] + (size_t)2 * EE * HH;

        sgemm64<<<dim3(4, 16, 2), 256>>>(x, W1, PQ, NA * NB, HH, EE,
                                         (size_t)EE * HH, (size_t)NA * NB * HH);
        sgemm64<<<dim3(1, 16, 1), 256>>>(rbf_W, W3, Wg, GG, HH, EE, 0, 0);
        bias0_kernel<<<4, 256>>>(W3, bin[mlp], rbf_b);
        pack_wg_kernel<<<(1024 * 32 + 255) / 256, 256>>>(wgt);

        h0_mma<<<dim3(HH / 128, MROWS / 128), 256>>>(gHi, gLo, (const uint4*)wgt,
                                                     fHiA, fLoA);

        unsigned* curHi = fHiA; unsigned* curLo = fLoA;
        unsigned* nxtHi = fHiB; unsigned* nxtLo = fLoB;
        for (int l = 0; l < L; l++) {
            size_t zo = (size_t)(mlp * 3 + l) * WW;
            int last = (l == L - 1) ? 1 : 0;
            mma_layer<<<dim3(HH / 128, MROWS / 128), 256, DSMEM_BYTES>>>(
                curHi, curLo,
                (const uint4*)(Wt + zo),
                bh[mlp] + (size_t)l * HH, nxtHi, nxtLo,
                Wout[mlp], partp, last);
            unsigned* t1 = curHi; curHi = nxtHi; nxtHi = t1;
            unsigned* t2 = curLo; curLo = nxtLo; nxtLo = t2;
        }

        reduce2<<<NA * NB, 128>>>(partp, bout[mlp], mask, vec_hat, out, mlp);
    }

    energy_kernel<<<1, 64>>>(out);
}